// round 13
// baseline (speedup 1.0000x reference)
#include <cuda_runtime.h>
#include <cuda_fp16.h>
#include <math.h>
#include <stdint.h>

#define BB 4
#define TT 4096
#define DD 384
#define HD 64
#define BQ 64
#define BS 64

// Scratch (allocation-free). NEVER take these addresses in host code.
// g_k / g_v are stored XOR-swizzled: element (t,d) lives at column d ^ ((t&7)<<3).
__device__ __half g_xh[(size_t)BB * TT * DD];
__device__ __half g_wq[(size_t)HD * DD];
__device__ __half g_wk[(size_t)HD * DD];
__device__ __half g_wv[(size_t)DD * DD];
__device__ __half g_q[(size_t)BB * TT * HD];     // pre-scaled by 0.125 (via Wq), NOT swizzled
__device__ __half g_k[(size_t)BB * TT * HD];     // swizzled
__device__ __half g_v[(size_t)BB * TT * DD];     // swizzled, [b][t][d]

__device__ __forceinline__ void mma16(float* c, const uint32_t* a, uint32_t b0, uint32_t b1) {
    asm volatile(
        "mma.sync.aligned.m16n8k16.row.col.f32.f16.f16.f32 "
        "{%0,%1,%2,%3}, {%4,%5,%6,%7}, {%8,%9}, {%0,%1,%2,%3};\n"
        : "+f"(c[0]), "+f"(c[1]), "+f"(c[2]), "+f"(c[3])
        : "r"(a[0]), "r"(a[1]), "r"(a[2]), "r"(a[3]), "r"(b0), "r"(b1));
}

__device__ __forceinline__ void ldsm4(uint32_t& r0, uint32_t& r1, uint32_t& r2, uint32_t& r3,
                                      uint32_t addr) {
    asm volatile("ldmatrix.sync.aligned.m8n8.x4.shared.b16 {%0,%1,%2,%3}, [%4];"
                 : "=r"(r0), "=r"(r1), "=r"(r2), "=r"(r3) : "r"(addr) : "memory");
}

__device__ __forceinline__ void ldsm4t(uint32_t& r0, uint32_t& r1, uint32_t& r2, uint32_t& r3,
                                       uint32_t addr) {
    asm volatile("ldmatrix.sync.aligned.m8n8.x4.trans.shared.b16 {%0,%1,%2,%3}, [%4];"
                 : "=r"(r0), "=r"(r1), "=r"(r2), "=r"(r3) : "r"(addr) : "memory");
}

__device__ __forceinline__ void cp16(uint32_t dsh, const void* src) {
    asm volatile("cp.async.cg.shared.global [%0], [%1], 16;\n" :: "r"(dsh), "l"(src));
}

__device__ __forceinline__ void bulkcp(uint32_t dst, const void* src, uint32_t bytes, uint32_t mbar) {
    asm volatile("cp.async.bulk.shared::cta.global.mbarrier::complete_tx::bytes [%0], [%1], %2, [%3];"
                 :: "r"(dst), "l"(src), "r"(bytes), "r"(mbar) : "memory");
}

__device__ __forceinline__ void mbar_init(uint32_t mbar, uint32_t count) {
    asm volatile("mbarrier.init.shared.b64 [%0], %1;" :: "r"(mbar), "r"(count) : "memory");
}

__device__ __forceinline__ void mbar_expect_tx(uint32_t mbar, uint32_t bytes) {
    asm volatile("mbarrier.arrive.expect_tx.shared.b64 _, [%0], %1;" :: "r"(mbar), "r"(bytes) : "memory");
}

__device__ __forceinline__ void mbar_wait(uint32_t mbar, uint32_t parity) {
    asm volatile(
        "{\n\t.reg .pred P;\n\t"
        "WAIT_%=:\n\t"
        "mbarrier.try_wait.parity.acquire.cta.shared::cta.b64 P, [%0], %1, 0x989680;\n\t"
        "@!P bra WAIT_%=;\n\t"
        "}" :: "r"(mbar), "r"(parity) : "memory");
}

__device__ __forceinline__ void barsync(int id) {
    asm volatile("bar.sync %0, 128;" :: "r"(id) : "memory");
}

// ---------------- fused fp32 -> fp16 conversion (one launch) ----------------
#define NX4 (BB * TT * DD / 4)
#define NW4 (HD * DD / 4)
#define NV4 (DD * DD / 4)
#define XBLK (NX4 / 256)
#define WBLK (NW4 / 256)
#define VBLK (NV4 / 256)

__global__ void __launch_bounds__(256) to_half_all(
    const float* __restrict__ x, const float* __restrict__ Wk,
    const float* __restrict__ Wq, const float* __restrict__ Wv)
{
    int bid = blockIdx.x;
    const float* s; __half* d; int base; float sc = 1.f;
    if (bid < XBLK)                  { s = x;  d = g_xh; base = 0; }
    else if (bid < XBLK + WBLK)      { s = Wq; d = g_wq; base = XBLK; sc = 0.125f; }
    else if (bid < XBLK + 2 * WBLK)  { s = Wk; d = g_wk; base = XBLK + WBLK; }
    else                             { s = Wv; d = g_wv; base = XBLK + 2 * WBLK; }
    int i = (bid - base) * 256 + threadIdx.x;
    float4 v = ((const float4*)s)[i];
    __half2 h0 = __floats2half2_rn(v.x * sc, v.y * sc);
    __half2 h1 = __floats2half2_rn(v.z * sc, v.w * sc);
    uint2 o;
    o.x = *(uint32_t*)&h0;
    o.y = *(uint32_t*)&h1;
    ((uint2*)d)[i] = o;
}

// ---------------- fp16 mma projection GEMM (k/v written swizzled) ----------------
#define XS 72
#define WS 72
#define X_TILE (128 * XS)
#define W_TILE (64 * WS)
#define PROJ_SMEM_HALFS (2 * (X_TILE + W_TILE))
#define PROJ_SMEM_BYTES (PROJ_SMEM_HALFS * 2)

__device__ __forceinline__ void proj_stage(__half* smp, const __half* X, const __half* W,
                                           int bm, int bn, int k0, int buf, int tid)
{
    __half* xb = smp + buf * (X_TILE + W_TILE);
    __half* wb = xb + X_TILE;
    uint32_t xbase = (uint32_t)__cvta_generic_to_shared(xb);
    uint32_t wbase = (uint32_t)__cvta_generic_to_shared(wb);
#pragma unroll
    for (int it = 0; it < 4; it++) {
        int i = tid + 256 * it;
        int r = i >> 3, c = i & 7;
        cp16(xbase + (uint32_t)(r * XS + c * 8) * 2,
             X + (size_t)(bm * 128 + r) * DD + k0 + c * 8);
    }
#pragma unroll
    for (int it = 0; it < 2; it++) {
        int i = tid + 256 * it;
        int r = i >> 3, c = i & 7;
        cp16(wbase + (uint32_t)(r * WS + c * 8) * 2,
             W + (size_t)(bn * 64 + r) * DD + k0 + c * 8);
    }
}

__global__ void __launch_bounds__(256) proj_gemm(int which_base)
{
    extern __shared__ __half smp[];
    const int z = blockIdx.z;
    const int which = which_base + z;
    const __half* X = g_xh;
    const __half* W = (which == 0) ? g_wq : (which == 1) ? g_wk : g_wv;
    __half* Y = (which == 0) ? g_q : (which == 1) ? g_k : g_v;
    const int N = (which < 2) ? HD : DD;

    const int bm = blockIdx.y;
    const int bn = blockIdx.x;
    const int tid = threadIdx.x;
    const int w = tid >> 5, l = tid & 31;
    const int wm = w >> 1, wn = w & 1;
    const int g = l >> 2, q4 = l & 3;

    float c[2][4][4];
#pragma unroll
    for (int mt = 0; mt < 2; mt++)
#pragma unroll
        for (int j = 0; j < 4; j++) { c[mt][j][0] = c[mt][j][1] = c[mt][j][2] = c[mt][j][3] = 0.f; }

    proj_stage(smp, X, W, bm, bn, 0, 0, tid);
    asm volatile("cp.async.commit_group;\n");

    const int nC = DD / 64;
    for (int cc = 0; cc < nC; cc++) {
        __syncthreads();
        if (cc + 1 < nC) {
            proj_stage(smp, X, W, bm, bn, (cc + 1) * 64, (cc + 1) & 1, tid);
            asm volatile("cp.async.commit_group;\n");
            asm volatile("cp.async.wait_group 1;\n");
        } else {
            asm volatile("cp.async.wait_group 0;\n");
        }
        __syncthreads();

        const __half* xb = smp + (cc & 1) * (X_TILE + W_TILE);
        const __half* wb = xb + X_TILE;
#pragma unroll
        for (int kk = 0; kk < 4; kk++) {
            const int k = kk * 16;
            uint32_t a[2][4];
#pragma unroll
            for (int mt = 0; mt < 2; mt++) {
                int r0 = wm * 32 + 16 * mt + g;
                a[mt][0] = *(const uint32_t*)&xb[r0 * XS + k + 2 * q4];
                a[mt][1] = *(const uint32_t*)&xb[(r0 + 8) * XS + k + 2 * q4];
                a[mt][2] = *(const uint32_t*)&xb[r0 * XS + k + 2 * q4 + 8];
                a[mt][3] = *(const uint32_t*)&xb[(r0 + 8) * XS + k + 2 * q4 + 8];
            }
#pragma unroll
            for (int j = 0; j < 4; j++) {
                int n = wn * 32 + 8 * j + g;
                uint32_t b0 = *(const uint32_t*)&wb[n * WS + k + 2 * q4];
                uint32_t b1 = *(const uint32_t*)&wb[n * WS + k + 2 * q4 + 8];
#pragma unroll
                for (int mt = 0; mt < 2; mt++) mma16(c[mt][j], a[mt], b0, b1);
            }
        }
    }

    const int swz = (which >= 1) ? (g << 3) : 0;
#pragma unroll
    for (int mt = 0; mt < 2; mt++) {
        int r0 = bm * 128 + wm * 32 + 16 * mt + g;
#pragma unroll
        for (int j = 0; j < 4; j++) {
            int col = (bn * 64 + wn * 32 + 8 * j + 2 * q4) ^ swz;
            *(__half2*)&Y[(size_t)r0 * N + col] = __floats2half2_rn(c[mt][j][0], c[mt][j][1]);
            *(__half2*)&Y[(size_t)(r0 + 8) * N + col] = __floats2half2_rn(c[mt][j][2], c[mt][j][3]);
        }
    }
}

// ---------------- flash attention: 512 threads, 4 qw-groups x 4 dw (key/d split) ----------------
#define VST 384
#define KST 64
#define PST 72
#define VT_TILE (64 * VST)
#define KS_TILE (64 * KST)
#define VT_OFF 0
#define KS_OFF (2 * VT_TILE)
#define PS_OFF (KS_OFF + 2 * KS_TILE)
#define SMEM_HALFS (PS_OFF + 4 * 16 * PST)
#define SMEM_BYTES (SMEM_HALFS * 2)
#define V_BYTES (64 * DD * 2)
#define K_BYTES (64 * HD * 2)
#define STAGE_BYTES (V_BYTES + K_BYTES)

__global__ void __launch_bounds__(512, 1) flash2(float* __restrict__ O)
{
    extern __shared__ __half smh[];
    __shared__ __align__(8) uint64_t fmbar[2];
    __shared__ float red[256];

    const int b = blockIdx.y;
    const int qb = (int)gridDim.x - 1 - (int)blockIdx.x;
    const int q0 = qb * BQ;
    const int tid = threadIdx.x;
    const int w = tid >> 5, l = tid & 31;
    const int qw = w >> 2, dw = w & 3;       // qw: 16-row group (spans 4 SMSPs); dw: key/d split
    const int g = l >> 2, q4 = l & 3;

    const __half* Qb = g_q + ((size_t)b * TT + q0) * HD;
    const __half* Kb = g_k + (size_t)b * TT * HD;
    const __half* Vb = g_v + (size_t)b * TT * DD;

    __half* Ps = smh + PS_OFF + qw * (16 * PST);

    const uint32_t smb = (uint32_t)__cvta_generic_to_shared(smh);
    const uint32_t mb0 = (uint32_t)__cvta_generic_to_shared(&fmbar[0]);
    const uint32_t mb1 = (uint32_t)__cvta_generic_to_shared(&fmbar[1]);

    // ldmatrix lane geometry
    const int mm = l >> 3;
    const int rowB = (l & 7) + ((mm >> 1) << 3);   // K (non-trans B): t index
    const int colB = (mm & 1) << 3;
    const int rowA = (l & 7) + ((mm & 1) << 3);    // P (A)
    const int colA = (mm >> 1) << 3;
    const int rowT = (l & 7) + ((mm & 1) << 3);    // V (trans B): t index
    const int colT = (l >> 4) << 3;                // d index
    const int sw = (l & 7) << 3;                   // per-lane column swizzle (halfs)
    const uint32_t psa = smb + (uint32_t)(PS_OFF + qw * 16 * PST + rowA * PST + colA) * 2;

    const int redi = (qw * 4 + dw) * 8 + g;        // this warp's partial slot
    const int redbase = qw * 32 + g;               // + dw2*8 to read all partials

    if (tid == 0) {
        mbar_init(mb0, 1);
        mbar_init(mb1, 1);
        asm volatile("fence.proxy.async.shared::cta;" ::: "memory");
    }
    __syncthreads();

    uint32_t qa[4][4];
    const int qr0 = qw * 16 + g;
#pragma unroll
    for (int kk = 0; kk < 4; kk++) {
        qa[kk][0] = *(const uint32_t*)&Qb[(size_t)qr0 * HD + 16 * kk + 2 * q4];
        qa[kk][1] = *(const uint32_t*)&Qb[(size_t)(qr0 + 8) * HD + 16 * kk + 2 * q4];
        qa[kk][2] = *(const uint32_t*)&Qb[(size_t)qr0 * HD + 16 * kk + 2 * q4 + 8];
        qa[kk][3] = *(const uint32_t*)&Qb[(size_t)(qr0 + 8) * HD + 16 * kk + 2 * q4 + 8];
    }

    float co[12][4];
#pragma unroll
    for (int j = 0; j < 12; j++) { co[j][0] = co[j][1] = co[j][2] = co[j][3] = 0.f; }
    float m0 = -1e30f, m1 = -1e30f, l0 = 0.f, l1 = 0.f;

    const int nT = (q0 + BQ) / BS;
    const int q_last = q0 + qw * 16 + 15;
    const int row0 = q0 + qw * 16 + g;
    const int row1 = row0 + 8;
    const int d0base = dw * 96;

    // stage tile 0 into buf 0: exactly 2 bulk copies
    if (tid == 0) {
        mbar_expect_tx(mb0, STAGE_BYTES);
        bulkcp(smb + (uint32_t)VT_OFF * 2, Vb, V_BYTES, mb0);
        bulkcp(smb + (uint32_t)KS_OFF * 2, Kb, K_BYTES, mb0);
    }

    for (int t = 0; t < nT; t++) {
        if (t + 1 < nT && tid == 0) {
            const int buf = (t + 1) & 1;
            const uint32_t mb = buf ? mb1 : mb0;
            const int s1 = (t + 1) * BS;
            mbar_expect_tx(mb, STAGE_BYTES);
            bulkcp(smb + (uint32_t)(VT_OFF + buf * VT_TILE) * 2, Vb + (size_t)s1 * DD, V_BYTES, mb);
            bulkcp(smb + (uint32_t)(KS_OFF + buf * KS_TILE) * 2, Kb + (size_t)s1 * HD, K_BYTES, mb);
        }

        mbar_wait((t & 1) ? mb1 : mb0, (t >> 1) & 1);

        const int s0 = t * BS;
        if (s0 <= q_last) {
            const uint32_t ksb = smb + (uint32_t)(KS_OFF + (t & 1) * KS_TILE + rowB * KST) * 2;
            const uint32_t vtb = smb + (uint32_t)(VT_OFF + (t & 1) * VT_TILE + rowT * VST) * 2;

            // ---- S = Q K^T for this warp's 16 keys: 4 ldsm4 + 8 mma ----
            float cs[2][4];
            cs[0][0] = cs[0][1] = cs[0][2] = cs[0][3] = 0.f;
            cs[1][0] = cs[1][1] = cs[1][2] = cs[1][3] = 0.f;
#pragma unroll
            for (int kk = 0; kk < 4; kk++) {
                uint32_t b0, b1, b2, b3;
                ldsm4(b0, b1, b2, b3,
                      ksb + (uint32_t)(dw * 16 * KST + ((colB + kk * 16) ^ sw)) * 2);
                mma16(cs[0], qa[kk], b0, b1);
                mma16(cs[1], qa[kk], b2, b3);
            }

            // ---- mask + partial row max over 16 keys ----
            const bool needmask = (s0 + dw * 16 + 15) > (q0 + qw * 16);
            float mx0 = -1e30f, mx1 = -1e30f;
#pragma unroll
            for (int jl = 0; jl < 2; jl++) {
                int c0 = s0 + dw * 16 + 8 * jl + 2 * q4;
                float s00 = cs[jl][0], s01 = cs[jl][1];
                float s10 = cs[jl][2], s11 = cs[jl][3];
                if (needmask) {
                    if (c0 > row0)     s00 = -1e30f;
                    if (c0 + 1 > row0) s01 = -1e30f;
                    if (c0 > row1)     s10 = -1e30f;
                    if (c0 + 1 > row1) s11 = -1e30f;
                }
                cs[jl][0] = s00; cs[jl][1] = s01; cs[jl][2] = s10; cs[jl][3] = s11;
                mx0 = fmaxf(mx0, fmaxf(s00, s01));
                mx1 = fmaxf(mx1, fmaxf(s10, s11));
            }
            mx0 = fmaxf(mx0, __shfl_xor_sync(0xffffffffu, mx0, 1, 4));
            mx0 = fmaxf(mx0, __shfl_xor_sync(0xffffffffu, mx0, 2, 4));
            mx1 = fmaxf(mx1, __shfl_xor_sync(0xffffffffu, mx1, 1, 4));
            mx1 = fmaxf(mx1, __shfl_xor_sync(0xffffffffu, mx1, 2, 4));

            // ---- cross-dw max exchange ----
            if (q4 == 0) { red[redi] = mx0; red[128 + redi] = mx1; }
            barsync(1 + qw);
            float gm0 = mx0, gm1 = mx1;
#pragma unroll
            for (int d2 = 0; d2 < 4; d2++) {
                gm0 = fmaxf(gm0, red[redbase + d2 * 8]);
                gm1 = fmaxf(gm1, red[128 + redbase + d2 * 8]);
            }

            float mn0 = fmaxf(m0, gm0), mn1 = fmaxf(m1, gm1);
            float cr0 = __expf(m0 - mn0), cr1 = __expf(m1 - mn1);
            m0 = mn0; m1 = mn1;

            // ---- P = exp(S - m) for this warp's 16 keys ----
            float sum0 = 0.f, sum1 = 0.f;
#pragma unroll
            for (int jl = 0; jl < 2; jl++) {
                float p00 = __expf(cs[jl][0] - mn0), p01 = __expf(cs[jl][1] - mn0);
                float p10 = __expf(cs[jl][2] - mn1), p11 = __expf(cs[jl][3] - mn1);
                sum0 += p00 + p01; sum1 += p10 + p11;
                *(__half2*)&Ps[g * PST + dw * 16 + 8 * jl + 2 * q4]       = __floats2half2_rn(p00, p01);
                *(__half2*)&Ps[(g + 8) * PST + dw * 16 + 8 * jl + 2 * q4] = __floats2half2_rn(p10, p11);
            }
            sum0 += __shfl_xor_sync(0xffffffffu, sum0, 1, 4);
            sum0 += __shfl_xor_sync(0xffffffffu, sum0, 2, 4);
            sum1 += __shfl_xor_sync(0xffffffffu, sum1, 1, 4);
            sum1 += __shfl_xor_sync(0xffffffffu, sum1, 2, 4);
            l0 = l0 * cr0 + sum0;     // warp-local partial l over its 16 keys
            l1 = l1 * cr1 + sum1;

            if (!__all_sync(0xffffffffu, (cr0 == 1.f) & (cr1 == 1.f))) {
#pragma unroll
                for (int j = 0; j < 12; j++) {
                    co[j][0] *= cr0; co[j][1] *= cr0;
                    co[j][2] *= cr1; co[j][3] *= cr1;
                }
            }
            barsync(1 + qw);   // all dw halves of P visible

            // ---- O += P V over this warp's 96 d-cols ----
#pragma unroll
            for (int kc = 0; kc < 4; kc++) {
                uint32_t a[4];
                ldsm4(a[0], a[1], a[2], a[3], psa + (uint32_t)(kc * 16) * 2);
#pragma unroll
                for (int jp = 0; jp < 6; jp++) {
                    uint32_t b0, b1, b2, b3;
                    ldsm4t(b0, b1, b2, b3,
                           vtb + (uint32_t)(kc * 16 * VST + ((d0base + colT + jp * 16) ^ sw)) * 2);
                    mma16(co[2 * jp], a, b0, b1);
                    mma16(co[2 * jp + 1], a, b2, b3);
                }
            }
        }
        __syncthreads();   // staging buffer t&1 free for tile t+2; also protects red/P reuse
    }

    // combine l partials across dw
    if (q4 == 0) { red[redi] = l0; red[128 + redi] = l1; }
    __syncthreads();
    float L0 = 0.f, L1 = 0.f;
#pragma unroll
    for (int d2 = 0; d2 < 4; d2++) {
        L0 += red[redbase + d2 * 8];
        L1 += red[128 + redbase + d2 * 8];
    }

    const float i0 = 1.f / L0, i1 = 1.f / L1;
    float* O0 = O + ((size_t)b * TT + row0) * DD + d0base;
    float* O1 = O + ((size_t)b * TT + row1) * DD + d0base;
#pragma unroll
    for (int j = 0; j < 12; j++) {
        *(float2*)&O0[8 * j + 2 * q4] = make_float2(co[j][0] * i0, co[j][1] * i0);
        *(float2*)&O1[8 * j + 2 * q4] = make_float2(co[j][2] * i1, co[j][3] * i1);
    }
}

extern "C" void kernel_launch(void* const* d_in, const int* in_sizes, int n_in,
                              void* d_out, int out_size)
{
    const float* x  = (const float*)d_in[0];
    const float* Wk = (const float*)d_in[1];
    const float* Wq = (const float*)d_in[2];
    const float* Wv = (const float*)d_in[3];
    float* out = (float*)d_out;

    to_half_all<<<XBLK + 2 * WBLK + VBLK, 256>>>(x, Wk, Wq, Wv);

    cudaFuncSetAttribute(proj_gemm, cudaFuncAttributeMaxDynamicSharedMemorySize, PROJ_SMEM_BYTES);
    proj_gemm<<<dim3(1, 128, 2), 256, PROJ_SMEM_BYTES>>>(0);
    proj_gemm<<<dim3(6, 128, 1), 256, PROJ_SMEM_BYTES>>>(2);

    cudaFuncSetAttribute(flash2, cudaFuncAttributeMaxDynamicSharedMemorySize, SMEM_BYTES);
    flash2<<<dim3(TT / BQ, BB), 512, SMEM_BYTES>>>(out);
}

// round 14
// speedup vs baseline: 1.0039x; 1.0039x over previous
#include <cuda_runtime.h>
#include <cuda_fp16.h>
#include <math.h>
#include <stdint.h>

#define BB 4
#define TT 4096
#define DD 384
#define HD 64
#define BQ 64
#define BS 64

// Scratch (allocation-free). NEVER take these addresses in host code.
// g_k / g_v are stored XOR-swizzled: element (t,d) lives at column d ^ ((t&7)<<3).
__device__ __half g_xh[(size_t)BB * TT * DD];
__device__ __half g_wq[(size_t)HD * DD];
__device__ __half g_wk[(size_t)HD * DD];
__device__ __half g_wv[(size_t)DD * DD];
__device__ __half g_q[(size_t)BB * TT * HD];     // pre-scaled by 0.125 (via Wq), NOT swizzled
__device__ __half g_k[(size_t)BB * TT * HD];     // swizzled
__device__ __half g_v[(size_t)BB * TT * DD];     // swizzled, [b][t][d]

__device__ __forceinline__ void mma16(float* c, const uint32_t* a, uint32_t b0, uint32_t b1) {
    asm volatile(
        "mma.sync.aligned.m16n8k16.row.col.f32.f16.f16.f32 "
        "{%0,%1,%2,%3}, {%4,%5,%6,%7}, {%8,%9}, {%0,%1,%2,%3};\n"
        : "+f"(c[0]), "+f"(c[1]), "+f"(c[2]), "+f"(c[3])
        : "r"(a[0]), "r"(a[1]), "r"(a[2]), "r"(a[3]), "r"(b0), "r"(b1));
}

__device__ __forceinline__ void ldsm4(uint32_t& r0, uint32_t& r1, uint32_t& r2, uint32_t& r3,
                                      uint32_t addr) {
    asm volatile("ldmatrix.sync.aligned.m8n8.x4.shared.b16 {%0,%1,%2,%3}, [%4];"
                 : "=r"(r0), "=r"(r1), "=r"(r2), "=r"(r3) : "r"(addr) : "memory");
}

__device__ __forceinline__ void ldsm4t(uint32_t& r0, uint32_t& r1, uint32_t& r2, uint32_t& r3,
                                       uint32_t addr) {
    asm volatile("ldmatrix.sync.aligned.m8n8.x4.trans.shared.b16 {%0,%1,%2,%3}, [%4];"
                 : "=r"(r0), "=r"(r1), "=r"(r2), "=r"(r3) : "r"(addr) : "memory");
}

__device__ __forceinline__ void cp16(uint32_t dsh, const void* src) {
    asm volatile("cp.async.cg.shared.global [%0], [%1], 16;\n" :: "r"(dsh), "l"(src));
}

__device__ __forceinline__ void bulkcp(uint32_t dst, const void* src, uint32_t bytes, uint32_t mbar) {
    asm volatile("cp.async.bulk.shared::cta.global.mbarrier::complete_tx::bytes [%0], [%1], %2, [%3];"
                 :: "r"(dst), "l"(src), "r"(bytes), "r"(mbar) : "memory");
}

__device__ __forceinline__ void mbar_init(uint32_t mbar, uint32_t count) {
    asm volatile("mbarrier.init.shared.b64 [%0], %1;" :: "r"(mbar), "r"(count) : "memory");
}

__device__ __forceinline__ void mbar_expect_tx(uint32_t mbar, uint32_t bytes) {
    asm volatile("mbarrier.arrive.expect_tx.shared.b64 _, [%0], %1;" :: "r"(mbar), "r"(bytes) : "memory");
}

__device__ __forceinline__ void mbar_wait(uint32_t mbar, uint32_t parity) {
    asm volatile(
        "{\n\t.reg .pred P;\n\t"
        "WAIT_%=:\n\t"
        "mbarrier.try_wait.parity.acquire.cta.shared::cta.b64 P, [%0], %1, 0x989680;\n\t"
        "@!P bra WAIT_%=;\n\t"
        "}" :: "r"(mbar), "r"(parity) : "memory");
}

__device__ __forceinline__ void barsync(int id) {
    asm volatile("bar.sync %0, 128;" :: "r"(id) : "memory");
}

// ---------------- fused fp32 -> fp16 conversion (one launch) ----------------
#define NX4 (BB * TT * DD / 4)
#define NW4 (HD * DD / 4)
#define NV4 (DD * DD / 4)
#define XBLK (NX4 / 256)
#define WBLK (NW4 / 256)
#define VBLK (NV4 / 256)

__global__ void __launch_bounds__(256) to_half_all(
    const float* __restrict__ x, const float* __restrict__ Wk,
    const float* __restrict__ Wq, const float* __restrict__ Wv)
{
    int bid = blockIdx.x;
    const float* s; __half* d; int base; float sc = 1.f;
    if (bid < XBLK)                  { s = x;  d = g_xh; base = 0; }
    else if (bid < XBLK + WBLK)      { s = Wq; d = g_wq; base = XBLK; sc = 0.125f; }
    else if (bid < XBLK + 2 * WBLK)  { s = Wk; d = g_wk; base = XBLK + WBLK; }
    else                             { s = Wv; d = g_wv; base = XBLK + 2 * WBLK; }
    int i = (bid - base) * 256 + threadIdx.x;
    float4 v = ((const float4*)s)[i];
    __half2 h0 = __floats2half2_rn(v.x * sc, v.y * sc);
    __half2 h1 = __floats2half2_rn(v.z * sc, v.w * sc);
    uint2 o;
    o.x = *(uint32_t*)&h0;
    o.y = *(uint32_t*)&h1;
    ((uint2*)d)[i] = o;
}

// ---------------- fp16 mma projection GEMM (k/v written swizzled) ----------------
#define XS 72
#define WS 72
#define X_TILE (128 * XS)
#define W_TILE (64 * WS)
#define PROJ_SMEM_HALFS (2 * (X_TILE + W_TILE))
#define PROJ_SMEM_BYTES (PROJ_SMEM_HALFS * 2)

__device__ __forceinline__ void proj_stage(__half* smp, const __half* X, const __half* W,
                                           int bm, int bn, int k0, int buf, int tid)
{
    __half* xb = smp + buf * (X_TILE + W_TILE);
    __half* wb = xb + X_TILE;
    uint32_t xbase = (uint32_t)__cvta_generic_to_shared(xb);
    uint32_t wbase = (uint32_t)__cvta_generic_to_shared(wb);
#pragma unroll
    for (int it = 0; it < 4; it++) {
        int i = tid + 256 * it;
        int r = i >> 3, c = i & 7;
        cp16(xbase + (uint32_t)(r * XS + c * 8) * 2,
             X + (size_t)(bm * 128 + r) * DD + k0 + c * 8);
    }
#pragma unroll
    for (int it = 0; it < 2; it++) {
        int i = tid + 256 * it;
        int r = i >> 3, c = i & 7;
        cp16(wbase + (uint32_t)(r * WS + c * 8) * 2,
             W + (size_t)(bn * 64 + r) * DD + k0 + c * 8);
    }
}

__global__ void __launch_bounds__(256) proj_gemm(int which_base)
{
    extern __shared__ __half smp[];
    const int z = blockIdx.z;
    const int which = which_base + z;
    const __half* X = g_xh;
    const __half* W = (which == 0) ? g_wq : (which == 1) ? g_wk : g_wv;
    __half* Y = (which == 0) ? g_q : (which == 1) ? g_k : g_v;
    const int N = (which < 2) ? HD : DD;

    const int bm = blockIdx.y;
    const int bn = blockIdx.x;
    const int tid = threadIdx.x;
    const int w = tid >> 5, l = tid & 31;
    const int wm = w >> 1, wn = w & 1;
    const int g = l >> 2, q4 = l & 3;

    float c[2][4][4];
#pragma unroll
    for (int mt = 0; mt < 2; mt++)
#pragma unroll
        for (int j = 0; j < 4; j++) { c[mt][j][0] = c[mt][j][1] = c[mt][j][2] = c[mt][j][3] = 0.f; }

    proj_stage(smp, X, W, bm, bn, 0, 0, tid);
    asm volatile("cp.async.commit_group;\n");

    const int nC = DD / 64;
    for (int cc = 0; cc < nC; cc++) {
        __syncthreads();
        if (cc + 1 < nC) {
            proj_stage(smp, X, W, bm, bn, (cc + 1) * 64, (cc + 1) & 1, tid);
            asm volatile("cp.async.commit_group;\n");
            asm volatile("cp.async.wait_group 1;\n");
        } else {
            asm volatile("cp.async.wait_group 0;\n");
        }
        __syncthreads();

        const __half* xb = smp + (cc & 1) * (X_TILE + W_TILE);
        const __half* wb = xb + X_TILE;
#pragma unroll
        for (int kk = 0; kk < 4; kk++) {
            const int k = kk * 16;
            uint32_t a[2][4];
#pragma unroll
            for (int mt = 0; mt < 2; mt++) {
                int r0 = wm * 32 + 16 * mt + g;
                a[mt][0] = *(const uint32_t*)&xb[r0 * XS + k + 2 * q4];
                a[mt][1] = *(const uint32_t*)&xb[(r0 + 8) * XS + k + 2 * q4];
                a[mt][2] = *(const uint32_t*)&xb[r0 * XS + k + 2 * q4 + 8];
                a[mt][3] = *(const uint32_t*)&xb[(r0 + 8) * XS + k + 2 * q4 + 8];
            }
#pragma unroll
            for (int j = 0; j < 4; j++) {
                int n = wn * 32 + 8 * j + g;
                uint32_t b0 = *(const uint32_t*)&wb[n * WS + k + 2 * q4];
                uint32_t b1 = *(const uint32_t*)&wb[n * WS + k + 2 * q4 + 8];
#pragma unroll
                for (int mt = 0; mt < 2; mt++) mma16(c[mt][j], a[mt], b0, b1);
            }
        }
    }

    const int swz = (which >= 1) ? (g << 3) : 0;
#pragma unroll
    for (int mt = 0; mt < 2; mt++) {
        int r0 = bm * 128 + wm * 32 + 16 * mt + g;
#pragma unroll
        for (int j = 0; j < 4; j++) {
            int col = (bn * 64 + wn * 32 + 8 * j + 2 * q4) ^ swz;
            *(__half2*)&Y[(size_t)r0 * N + col] = __floats2half2_rn(c[mt][j][0], c[mt][j][1]);
            *(__half2*)&Y[(size_t)(r0 + 8) * N + col] = __floats2half2_rn(c[mt][j][2], c[mt][j][3]);
        }
    }
}

// ---------------- flash attention: 512 threads, 4 qw-groups x 4 dw (key/d split) ----------------
#define VST 384
#define KST 64
#define PST 72
#define VT_TILE (64 * VST)
#define KS_TILE (64 * KST)
#define VT_OFF 0
#define KS_OFF (2 * VT_TILE)
#define PS_OFF (KS_OFF + 2 * KS_TILE)
#define SMEM_HALFS (PS_OFF + 4 * 16 * PST)
#define SMEM_BYTES (SMEM_HALFS * 2)
#define V_BYTES (64 * DD * 2)
#define K_BYTES (64 * HD * 2)
#define STAGE_BYTES (V_BYTES + K_BYTES)

__global__ void __launch_bounds__(512, 1) flash2(float* __restrict__ O)
{
    extern __shared__ __half smh[];
    __shared__ __align__(8) uint64_t fmbar[2];
    __shared__ float red[256];

    const int b = blockIdx.y;
    const int qb = (int)gridDim.x - 1 - (int)blockIdx.x;
    const int q0 = qb * BQ;
    const int tid = threadIdx.x;
    const int w = tid >> 5, l = tid & 31;
    const int qw = w >> 2, dw = w & 3;       // qw: 16-row group (spans 4 SMSPs); dw: key/d split
    const int g = l >> 2, q4 = l & 3;

    const __half* Qb = g_q + ((size_t)b * TT + q0) * HD;
    const __half* Kb = g_k + (size_t)b * TT * HD;
    const __half* Vb = g_v + (size_t)b * TT * DD;

    __half* Ps = smh + PS_OFF + qw * (16 * PST);

    const uint32_t smb = (uint32_t)__cvta_generic_to_shared(smh);
    const uint32_t mb0 = (uint32_t)__cvta_generic_to_shared(&fmbar[0]);
    const uint32_t mb1 = (uint32_t)__cvta_generic_to_shared(&fmbar[1]);

    // ldmatrix lane geometry
    const int mm = l >> 3;
    const int rowB = (l & 7) + ((mm >> 1) << 3);   // K (non-trans B): t index
    const int colB = (mm & 1) << 3;
    const int rowA = (l & 7) + ((mm & 1) << 3);    // P (A)
    const int colA = (mm >> 1) << 3;
    const int rowT = (l & 7) + ((mm & 1) << 3);    // V (trans B): t index
    const int colT = (l >> 4) << 3;                // d index
    const int sw = (l & 7) << 3;                   // per-lane column swizzle (halfs)
    const uint32_t psa = smb + (uint32_t)(PS_OFF + qw * 16 * PST + rowA * PST + colA) * 2;

    const int redi = (qw * 4 + dw) * 8 + g;        // this warp's partial slot
    const int redbase = qw * 32 + g;               // + dw2*8 to read all partials

    if (tid == 0) {
        mbar_init(mb0, 1);
        mbar_init(mb1, 1);
        asm volatile("fence.proxy.async.shared::cta;" ::: "memory");
    }
    __syncthreads();

    uint32_t qa[4][4];
    const int qr0 = qw * 16 + g;
#pragma unroll
    for (int kk = 0; kk < 4; kk++) {
        qa[kk][0] = *(const uint32_t*)&Qb[(size_t)qr0 * HD + 16 * kk + 2 * q4];
        qa[kk][1] = *(const uint32_t*)&Qb[(size_t)(qr0 + 8) * HD + 16 * kk + 2 * q4];
        qa[kk][2] = *(const uint32_t*)&Qb[(size_t)qr0 * HD + 16 * kk + 2 * q4 + 8];
        qa[kk][3] = *(const uint32_t*)&Qb[(size_t)(qr0 + 8) * HD + 16 * kk + 2 * q4 + 8];
    }

    float co[12][4];
#pragma unroll
    for (int j = 0; j < 12; j++) { co[j][0] = co[j][1] = co[j][2] = co[j][3] = 0.f; }
    float m0 = -1e30f, m1 = -1e30f, l0 = 0.f, l1 = 0.f;

    const int nT = (q0 + BQ) / BS;
    const int q_last = q0 + qw * 16 + 15;
    const int row0 = q0 + qw * 16 + g;
    const int row1 = row0 + 8;
    const int d0base = dw * 96;

    // stage tile 0 into buf 0: exactly 2 bulk copies
    if (tid == 0) {
        mbar_expect_tx(mb0, STAGE_BYTES);
        bulkcp(smb + (uint32_t)VT_OFF * 2, Vb, V_BYTES, mb0);
        bulkcp(smb + (uint32_t)KS_OFF * 2, Kb, K_BYTES, mb0);
    }

    for (int t = 0; t < nT; t++) {
        if (t + 1 < nT && tid == 0) {
            const int buf = (t + 1) & 1;
            const uint32_t mb = buf ? mb1 : mb0;
            const int s1 = (t + 1) * BS;
            mbar_expect_tx(mb, STAGE_BYTES);
            bulkcp(smb + (uint32_t)(VT_OFF + buf * VT_TILE) * 2, Vb + (size_t)s1 * DD, V_BYTES, mb);
            bulkcp(smb + (uint32_t)(KS_OFF + buf * KS_TILE) * 2, Kb + (size_t)s1 * HD, K_BYTES, mb);
        }

        mbar_wait((t & 1) ? mb1 : mb0, (t >> 1) & 1);

        const int s0 = t * BS;
        if (s0 <= q_last) {
            const uint32_t ksb = smb + (uint32_t)(KS_OFF + (t & 1) * KS_TILE + rowB * KST) * 2;
            const uint32_t vtb = smb + (uint32_t)(VT_OFF + (t & 1) * VT_TILE + rowT * VST) * 2;

            // ---- S = Q K^T for this warp's 16 keys: 4 ldsm4 + 8 mma ----
            float cs[2][4];
            cs[0][0] = cs[0][1] = cs[0][2] = cs[0][3] = 0.f;
            cs[1][0] = cs[1][1] = cs[1][2] = cs[1][3] = 0.f;
#pragma unroll
            for (int kk = 0; kk < 4; kk++) {
                uint32_t b0, b1, b2, b3;
                ldsm4(b0, b1, b2, b3,
                      ksb + (uint32_t)(dw * 16 * KST + ((colB + kk * 16) ^ sw)) * 2);
                mma16(cs[0], qa[kk], b0, b1);
                mma16(cs[1], qa[kk], b2, b3);
            }

            // ---- mask + partial row max over 16 keys ----
            const bool needmask = (s0 + dw * 16 + 15) > (q0 + qw * 16);
            float mx0 = -1e30f, mx1 = -1e30f;
#pragma unroll
            for (int jl = 0; jl < 2; jl++) {
                int c0 = s0 + dw * 16 + 8 * jl + 2 * q4;
                float s00 = cs[jl][0], s01 = cs[jl][1];
                float s10 = cs[jl][2], s11 = cs[jl][3];
                if (needmask) {
                    if (c0 > row0)     s00 = -1e30f;
                    if (c0 + 1 > row0) s01 = -1e30f;
                    if (c0 > row1)     s10 = -1e30f;
                    if (c0 + 1 > row1) s11 = -1e30f;
                }
                cs[jl][0] = s00; cs[jl][1] = s01; cs[jl][2] = s10; cs[jl][3] = s11;
                mx0 = fmaxf(mx0, fmaxf(s00, s01));
                mx1 = fmaxf(mx1, fmaxf(s10, s11));
            }
            mx0 = fmaxf(mx0, __shfl_xor_sync(0xffffffffu, mx0, 1, 4));
            mx0 = fmaxf(mx0, __shfl_xor_sync(0xffffffffu, mx0, 2, 4));
            mx1 = fmaxf(mx1, __shfl_xor_sync(0xffffffffu, mx1, 1, 4));
            mx1 = fmaxf(mx1, __shfl_xor_sync(0xffffffffu, mx1, 2, 4));

            // ---- cross-dw max exchange ----
            if (q4 == 0) { red[redi] = mx0; red[128 + redi] = mx1; }
            barsync(1 + qw);
            float gm0 = mx0, gm1 = mx1;
#pragma unroll
            for (int d2 = 0; d2 < 4; d2++) {
                gm0 = fmaxf(gm0, red[redbase + d2 * 8]);
                gm1 = fmaxf(gm1, red[128 + redbase + d2 * 8]);
            }

            float mn0 = fmaxf(m0, gm0), mn1 = fmaxf(m1, gm1);
            float cr0 = __expf(m0 - mn0), cr1 = __expf(m1 - mn1);
            m0 = mn0; m1 = mn1;

            // ---- P = exp(S - m) for this warp's 16 keys ----
            float sum0 = 0.f, sum1 = 0.f;
#pragma unroll
            for (int jl = 0; jl < 2; jl++) {
                float p00 = __expf(cs[jl][0] - mn0), p01 = __expf(cs[jl][1] - mn0);
                float p10 = __expf(cs[jl][2] - mn1), p11 = __expf(cs[jl][3] - mn1);
                sum0 += p00 + p01; sum1 += p10 + p11;
                *(__half2*)&Ps[g * PST + dw * 16 + 8 * jl + 2 * q4]       = __floats2half2_rn(p00, p01);
                *(__half2*)&Ps[(g + 8) * PST + dw * 16 + 8 * jl + 2 * q4] = __floats2half2_rn(p10, p11);
            }
            sum0 += __shfl_xor_sync(0xffffffffu, sum0, 1, 4);
            sum0 += __shfl_xor_sync(0xffffffffu, sum0, 2, 4);
            sum1 += __shfl_xor_sync(0xffffffffu, sum1, 1, 4);
            sum1 += __shfl_xor_sync(0xffffffffu, sum1, 2, 4);
            l0 = l0 * cr0 + sum0;     // warp-local partial l over its 16 keys
            l1 = l1 * cr1 + sum1;

            if (!__all_sync(0xffffffffu, (cr0 == 1.f) & (cr1 == 1.f))) {
#pragma unroll
                for (int j = 0; j < 12; j++) {
                    co[j][0] *= cr0; co[j][1] *= cr0;
                    co[j][2] *= cr1; co[j][3] *= cr1;
                }
            }
            barsync(1 + qw);   // all dw halves of P visible

            // ---- O += P V over this warp's 96 d-cols ----
#pragma unroll
            for (int kc = 0; kc < 4; kc++) {
                uint32_t a[4];
                ldsm4(a[0], a[1], a[2], a[3], psa + (uint32_t)(kc * 16) * 2);
#pragma unroll
                for (int jp = 0; jp < 6; jp++) {
                    uint32_t b0, b1, b2, b3;
                    ldsm4t(b0, b1, b2, b3,
                           vtb + (uint32_t)(kc * 16 * VST + ((d0base + colT + jp * 16) ^ sw)) * 2);
                    mma16(co[2 * jp], a, b0, b1);
                    mma16(co[2 * jp + 1], a, b2, b3);
                }
            }
        }
        __syncthreads();   // staging buffer t&1 free for tile t+2; also protects red/P reuse
    }

    // combine l partials across dw
    if (q4 == 0) { red[redi] = l0; red[128 + redi] = l1; }
    __syncthreads();
    float L0 = 0.f, L1 = 0.f;
#pragma unroll
    for (int d2 = 0; d2 < 4; d2++) {
        L0 += red[redbase + d2 * 8];
        L1 += red[128 + redbase + d2 * 8];
    }

    const float i0 = 1.f / L0, i1 = 1.f / L1;
    float* O0 = O + ((size_t)b * TT + row0) * DD + d0base;
    float* O1 = O + ((size_t)b * TT + row1) * DD + d0base;
#pragma unroll
    for (int j = 0; j < 12; j++) {
        *(float2*)&O0[8 * j + 2 * q4] = make_float2(co[j][0] * i0, co[j][1] * i0);
        *(float2*)&O1[8 * j + 2 * q4] = make_float2(co[j][2] * i1, co[j][3] * i1);
    }
}

extern "C" void kernel_launch(void* const* d_in, const int* in_sizes, int n_in,
                              void* d_out, int out_size)
{
    const float* x  = (const float*)d_in[0];
    const float* Wk = (const float*)d_in[1];
    const float* Wq = (const float*)d_in[2];
    const float* Wv = (const float*)d_in[3];
    float* out = (float*)d_out;

    to_half_all<<<XBLK + 2 * WBLK + VBLK, 256>>>(x, Wk, Wq, Wv);

    cudaFuncSetAttribute(proj_gemm, cudaFuncAttributeMaxDynamicSharedMemorySize, PROJ_SMEM_BYTES);
    proj_gemm<<<dim3(1, 128, 2), 256, PROJ_SMEM_BYTES>>>(0);
    proj_gemm<<<dim3(6, 128, 1), 256, PROJ_SMEM_BYTES>>>(2);

    cudaFuncSetAttribute(flash2, cudaFuncAttributeMaxDynamicSharedMemorySize, SMEM_BYTES);
    flash2<<<dim3(TT / BQ, BB), 512, SMEM_BYTES>>>(out);
}

// round 15
// speedup vs baseline: 1.1762x; 1.1717x over previous
#include <cuda_runtime.h>
#include <cuda_fp16.h>
#include <math.h>
#include <stdint.h>

#define BB 4
#define TT 4096
#define DD 384
#define HD 64
#define BQ 64
#define BS 64

// Scratch (allocation-free). NEVER take these addresses in host code.
// g_k / g_v are stored XOR-swizzled: element (t,d) lives at column d ^ ((t&7)<<3).
__device__ __half g_xh[(size_t)BB * TT * DD];
__device__ __half g_wq[(size_t)HD * DD];
__device__ __half g_wk[(size_t)HD * DD];
__device__ __half g_wv[(size_t)DD * DD];
__device__ __half g_q[(size_t)BB * TT * HD];     // pre-scaled by 0.125 (via Wq), NOT swizzled
__device__ __half g_k[(size_t)BB * TT * HD];     // swizzled
__device__ __half g_v[(size_t)BB * TT * DD];     // swizzled, [b][t][d]

__device__ __forceinline__ void mma16(float* c, const uint32_t* a, uint32_t b0, uint32_t b1) {
    asm volatile(
        "mma.sync.aligned.m16n8k16.row.col.f32.f16.f16.f32 "
        "{%0,%1,%2,%3}, {%4,%5,%6,%7}, {%8,%9}, {%0,%1,%2,%3};\n"
        : "+f"(c[0]), "+f"(c[1]), "+f"(c[2]), "+f"(c[3])
        : "r"(a[0]), "r"(a[1]), "r"(a[2]), "r"(a[3]), "r"(b0), "r"(b1));
}

__device__ __forceinline__ void ldsm4(uint32_t& r0, uint32_t& r1, uint32_t& r2, uint32_t& r3,
                                      uint32_t addr) {
    asm volatile("ldmatrix.sync.aligned.m8n8.x4.shared.b16 {%0,%1,%2,%3}, [%4];"
                 : "=r"(r0), "=r"(r1), "=r"(r2), "=r"(r3) : "r"(addr) : "memory");
}

__device__ __forceinline__ void ldsm4t(uint32_t& r0, uint32_t& r1, uint32_t& r2, uint32_t& r3,
                                       uint32_t addr) {
    asm volatile("ldmatrix.sync.aligned.m8n8.x4.trans.shared.b16 {%0,%1,%2,%3}, [%4];"
                 : "=r"(r0), "=r"(r1), "=r"(r2), "=r"(r3) : "r"(addr) : "memory");
}

__device__ __forceinline__ void cp16(uint32_t dsh, const void* src) {
    asm volatile("cp.async.cg.shared.global [%0], [%1], 16;\n" :: "r"(dsh), "l"(src));
}

__device__ __forceinline__ void bulkcp(uint32_t dst, const void* src, uint32_t bytes, uint32_t mbar) {
    asm volatile("cp.async.bulk.shared::cta.global.mbarrier::complete_tx::bytes [%0], [%1], %2, [%3];"
                 :: "r"(dst), "l"(src), "r"(bytes), "r"(mbar) : "memory");
}

__device__ __forceinline__ void mbar_init(uint32_t mbar, uint32_t count) {
    asm volatile("mbarrier.init.shared.b64 [%0], %1;" :: "r"(mbar), "r"(count) : "memory");
}

__device__ __forceinline__ void mbar_expect_tx(uint32_t mbar, uint32_t bytes) {
    asm volatile("mbarrier.arrive.expect_tx.shared.b64 _, [%0], %1;" :: "r"(mbar), "r"(bytes) : "memory");
}

__device__ __forceinline__ void mbar_wait(uint32_t mbar, uint32_t parity) {
    asm volatile(
        "{\n\t.reg .pred P;\n\t"
        "WAIT_%=:\n\t"
        "mbarrier.try_wait.parity.acquire.cta.shared::cta.b64 P, [%0], %1, 0x989680;\n\t"
        "@!P bra WAIT_%=;\n\t"
        "}" :: "r"(mbar), "r"(parity) : "memory");
}

__device__ __forceinline__ void barsync(int id) {
    asm volatile("bar.sync %0, 128;" :: "r"(id) : "memory");
}

// ---------------- fused fp32 -> fp16 conversion (one launch) ----------------
#define NX4 (BB * TT * DD / 4)
#define NW4 (HD * DD / 4)
#define NV4 (DD * DD / 4)
#define XBLK (NX4 / 256)
#define WBLK (NW4 / 256)
#define VBLK (NV4 / 256)

__global__ void __launch_bounds__(256) to_half_all(
    const float* __restrict__ x, const float* __restrict__ Wk,
    const float* __restrict__ Wq, const float* __restrict__ Wv)
{
    int bid = blockIdx.x;
    const float* s; __half* d; int base; float sc = 1.f;
    if (bid < XBLK)                  { s = x;  d = g_xh; base = 0; }
    else if (bid < XBLK + WBLK)      { s = Wq; d = g_wq; base = XBLK; sc = 0.125f; }
    else if (bid < XBLK + 2 * WBLK)  { s = Wk; d = g_wk; base = XBLK + WBLK; }
    else                             { s = Wv; d = g_wv; base = XBLK + 2 * WBLK; }
    int i = (bid - base) * 256 + threadIdx.x;
    float4 v = ((const float4*)s)[i];
    __half2 h0 = __floats2half2_rn(v.x * sc, v.y * sc);
    __half2 h1 = __floats2half2_rn(v.z * sc, v.w * sc);
    uint2 o;
    o.x = *(uint32_t*)&h0;
    o.y = *(uint32_t*)&h1;
    ((uint2*)d)[i] = o;
}

// ---------------- fp16 mma projection GEMM (k/v written swizzled) ----------------
#define XS 72
#define WS 72
#define X_TILE (128 * XS)
#define W_TILE (64 * WS)
#define PROJ_SMEM_HALFS (2 * (X_TILE + W_TILE))
#define PROJ_SMEM_BYTES (PROJ_SMEM_HALFS * 2)

__device__ __forceinline__ void proj_stage(__half* smp, const __half* X, const __half* W,
                                           int bm, int bn, int k0, int buf, int tid)
{
    __half* xb = smp + buf * (X_TILE + W_TILE);
    __half* wb = xb + X_TILE;
    uint32_t xbase = (uint32_t)__cvta_generic_to_shared(xb);
    uint32_t wbase = (uint32_t)__cvta_generic_to_shared(wb);
#pragma unroll
    for (int it = 0; it < 4; it++) {
        int i = tid + 256 * it;
        int r = i >> 3, c = i & 7;
        cp16(xbase + (uint32_t)(r * XS + c * 8) * 2,
             X + (size_t)(bm * 128 + r) * DD + k0 + c * 8);
    }
#pragma unroll
    for (int it = 0; it < 2; it++) {
        int i = tid + 256 * it;
        int r = i >> 3, c = i & 7;
        cp16(wbase + (uint32_t)(r * WS + c * 8) * 2,
             W + (size_t)(bn * 64 + r) * DD + k0 + c * 8);
    }
}

__global__ void __launch_bounds__(256) proj_gemm(int which_base)
{
    extern __shared__ __half smp[];
    const int z = blockIdx.z;
    const int which = which_base + z;
    const __half* X = g_xh;
    const __half* W = (which == 0) ? g_wq : (which == 1) ? g_wk : g_wv;
    __half* Y = (which == 0) ? g_q : (which == 1) ? g_k : g_v;
    const int N = (which < 2) ? HD : DD;

    const int bm = blockIdx.y;
    const int bn = blockIdx.x;
    const int tid = threadIdx.x;
    const int w = tid >> 5, l = tid & 31;
    const int wm = w >> 1, wn = w & 1;
    const int g = l >> 2, q4 = l & 3;

    float c[2][4][4];
#pragma unroll
    for (int mt = 0; mt < 2; mt++)
#pragma unroll
        for (int j = 0; j < 4; j++) { c[mt][j][0] = c[mt][j][1] = c[mt][j][2] = c[mt][j][3] = 0.f; }

    proj_stage(smp, X, W, bm, bn, 0, 0, tid);
    asm volatile("cp.async.commit_group;\n");

    const int nC = DD / 64;
    for (int cc = 0; cc < nC; cc++) {
        __syncthreads();
        if (cc + 1 < nC) {
            proj_stage(smp, X, W, bm, bn, (cc + 1) * 64, (cc + 1) & 1, tid);
            asm volatile("cp.async.commit_group;\n");
            asm volatile("cp.async.wait_group 1;\n");
        } else {
            asm volatile("cp.async.wait_group 0;\n");
        }
        __syncthreads();

        const __half* xb = smp + (cc & 1) * (X_TILE + W_TILE);
        const __half* wb = xb + X_TILE;
#pragma unroll
        for (int kk = 0; kk < 4; kk++) {
            const int k = kk * 16;
            uint32_t a[2][4];
#pragma unroll
            for (int mt = 0; mt < 2; mt++) {
                int r0 = wm * 32 + 16 * mt + g;
                a[mt][0] = *(const uint32_t*)&xb[r0 * XS + k + 2 * q4];
                a[mt][1] = *(const uint32_t*)&xb[(r0 + 8) * XS + k + 2 * q4];
                a[mt][2] = *(const uint32_t*)&xb[r0 * XS + k + 2 * q4 + 8];
                a[mt][3] = *(const uint32_t*)&xb[(r0 + 8) * XS + k + 2 * q4 + 8];
            }
#pragma unroll
            for (int j = 0; j < 4; j++) {
                int n = wn * 32 + 8 * j + g;
                uint32_t b0 = *(const uint32_t*)&wb[n * WS + k + 2 * q4];
                uint32_t b1 = *(const uint32_t*)&wb[n * WS + k + 2 * q4 + 8];
#pragma unroll
                for (int mt = 0; mt < 2; mt++) mma16(c[mt][j], a[mt], b0, b1);
            }
        }
    }

    const int swz = (which >= 1) ? (g << 3) : 0;
#pragma unroll
    for (int mt = 0; mt < 2; mt++) {
        int r0 = bm * 128 + wm * 32 + 16 * mt + g;
#pragma unroll
        for (int j = 0; j < 4; j++) {
            int col = (bn * 64 + wn * 32 + 8 * j + 2 * q4) ^ swz;
            *(__half2*)&Y[(size_t)r0 * N + col] = __floats2half2_rn(c[mt][j][0], c[mt][j][1]);
            *(__half2*)&Y[(size_t)(r0 + 8) * N + col] = __floats2half2_rn(c[mt][j][2], c[mt][j][3]);
        }
    }
}

// ---------------- flash attention: paired q-blocks (perfect causal balance) ----------------
#define VST 384
#define KST 64
#define PST 72
#define VT_TILE (64 * VST)
#define KS_TILE (64 * KST)
#define VT_OFF 0
#define KS_OFF (2 * VT_TILE)
#define PS_OFF (KS_OFF + 2 * KS_TILE)
#define SMEM_HALFS (PS_OFF + 4 * 16 * PST)
#define SMEM_BYTES (SMEM_HALFS * 2)
#define V_BYTES (64 * DD * 2)
#define K_BYTES (64 * HD * 2)
#define STAGE_BYTES (V_BYTES + K_BYTES)

__global__ void __launch_bounds__(512, 1) flash2(float* __restrict__ O)
{
    extern __shared__ __half smh[];
    __shared__ __align__(8) uint64_t fmbar[2];
    __shared__ float red[256];

    const int b = blockIdx.y;
    const int bx = blockIdx.x;               // 0..31; handles qb = 63-bx then qb = bx
    const int tid = threadIdx.x;
    const int w = tid >> 5, l = tid & 31;
    const int qw = w >> 2, dw = w & 3;
    const int g = l >> 2, q4 = l & 3;

    const __half* Kb = g_k + (size_t)b * TT * HD;
    const __half* Vb = g_v + (size_t)b * TT * DD;

    __half* Ps = smh + PS_OFF + qw * (16 * PST);

    const uint32_t smb = (uint32_t)__cvta_generic_to_shared(smh);
    const uint32_t mb0 = (uint32_t)__cvta_generic_to_shared(&fmbar[0]);
    const uint32_t mb1 = (uint32_t)__cvta_generic_to_shared(&fmbar[1]);

    // ldmatrix lane geometry
    const int mm = l >> 3;
    const int rowB = (l & 7) + ((mm >> 1) << 3);
    const int colB = (mm & 1) << 3;
    const int rowA = (l & 7) + ((mm & 1) << 3);
    const int colA = (mm >> 1) << 3;
    const int rowT = (l & 7) + ((mm & 1) << 3);
    const int colT = (l >> 4) << 3;
    const int sw = (l & 7) << 3;
    const uint32_t psa = smb + (uint32_t)(PS_OFF + qw * 16 * PST + rowA * PST + colA) * 2;

    const int redi = (qw * 4 + dw) * 8 + g;
    const int redbase = qw * 32 + g;
    const int d0base = dw * 96;

    if (tid == 0) {
        mbar_init(mb0, 1);
        mbar_init(mb1, 1);
        asm volatile("fence.proxy.async.shared::cta;" ::: "memory");
    }
    __syncthreads();

    // stage global tile 0 (pass 0, t = 0)
    if (tid == 0) {
        mbar_expect_tx(mb0, STAGE_BYTES);
        bulkcp(smb + (uint32_t)VT_OFF * 2, Vb, V_BYTES, mb0);
        bulkcp(smb + (uint32_t)KS_OFF * 2, Kb, K_BYTES, mb0);
    }
    int tc = 1;   // tiles staged (uniform)
    int ct = 0;   // tiles consumed (uniform)

#pragma unroll 1
    for (int pass = 0; pass < 2; pass++) {
        const int qb = pass ? bx : (63 - bx);
        const int q0 = qb * BQ;
        const int nT = qb + 1;
        const __half* Qb = g_q + ((size_t)b * TT + q0) * HD;

        uint32_t qa[4][4];
        const int qr0 = qw * 16 + g;
#pragma unroll
        for (int kk = 0; kk < 4; kk++) {
            qa[kk][0] = *(const uint32_t*)&Qb[(size_t)qr0 * HD + 16 * kk + 2 * q4];
            qa[kk][1] = *(const uint32_t*)&Qb[(size_t)(qr0 + 8) * HD + 16 * kk + 2 * q4];
            qa[kk][2] = *(const uint32_t*)&Qb[(size_t)qr0 * HD + 16 * kk + 2 * q4 + 8];
            qa[kk][3] = *(const uint32_t*)&Qb[(size_t)(qr0 + 8) * HD + 16 * kk + 2 * q4 + 8];
        }

        float co[12][4];
#pragma unroll
        for (int j = 0; j < 12; j++) { co[j][0] = co[j][1] = co[j][2] = co[j][3] = 0.f; }
        float m0 = -1e30f, m1 = -1e30f, l0 = 0.f, l1 = 0.f;

        const int q_last = q0 + qw * 16 + 15;
        const int row0 = q0 + qw * 16 + g;
        const int row1 = row0 + 8;

#pragma unroll 1
        for (int t = 0; t < nT; t++) {
            const bool have_next = (t + 1 < nT) || (pass == 0);
            if (have_next) {
                if (tid == 0) {
                    const int buf = tc & 1;
                    const uint32_t mb = buf ? mb1 : mb0;
                    const int s1 = (t + 1 < nT) ? (t + 1) * BS : 0;   // pass-1 tile 0
                    mbar_expect_tx(mb, STAGE_BYTES);
                    bulkcp(smb + (uint32_t)(VT_OFF + buf * VT_TILE) * 2,
                           Vb + (size_t)s1 * DD, V_BYTES, mb);
                    bulkcp(smb + (uint32_t)(KS_OFF + buf * KS_TILE) * 2,
                           Kb + (size_t)s1 * HD, K_BYTES, mb);
                }
                tc++;
            }

            const int cbuf = ct & 1;
            mbar_wait(cbuf ? mb1 : mb0, (ct >> 1) & 1);
            ct++;

            const int s0 = t * BS;
            if (s0 <= q_last) {
                const uint32_t ksb = smb + (uint32_t)(KS_OFF + cbuf * KS_TILE + rowB * KST) * 2;
                const uint32_t vtb = smb + (uint32_t)(VT_OFF + cbuf * VT_TILE + rowT * VST) * 2;

                // ---- S = Q K^T for this warp's 16 keys ----
                float cs[2][4];
                cs[0][0] = cs[0][1] = cs[0][2] = cs[0][3] = 0.f;
                cs[1][0] = cs[1][1] = cs[1][2] = cs[1][3] = 0.f;
#pragma unroll
                for (int kk = 0; kk < 4; kk++) {
                    uint32_t b0, b1, b2, b3;
                    ldsm4(b0, b1, b2, b3,
                          ksb + (uint32_t)(dw * 16 * KST + ((colB + kk * 16) ^ sw)) * 2);
                    mma16(cs[0], qa[kk], b0, b1);
                    mma16(cs[1], qa[kk], b2, b3);
                }

                const bool needmask = (s0 + dw * 16 + 15) > (q0 + qw * 16);
                float mx0 = -1e30f, mx1 = -1e30f;
#pragma unroll
                for (int jl = 0; jl < 2; jl++) {
                    int c0 = s0 + dw * 16 + 8 * jl + 2 * q4;
                    float s00 = cs[jl][0], s01 = cs[jl][1];
                    float s10 = cs[jl][2], s11 = cs[jl][3];
                    if (needmask) {
                        if (c0 > row0)     s00 = -1e30f;
                        if (c0 + 1 > row0) s01 = -1e30f;
                        if (c0 > row1)     s10 = -1e30f;
                        if (c0 + 1 > row1) s11 = -1e30f;
                    }
                    cs[jl][0] = s00; cs[jl][1] = s01; cs[jl][2] = s10; cs[jl][3] = s11;
                    mx0 = fmaxf(mx0, fmaxf(s00, s01));
                    mx1 = fmaxf(mx1, fmaxf(s10, s11));
                }
                mx0 = fmaxf(mx0, __shfl_xor_sync(0xffffffffu, mx0, 1, 4));
                mx0 = fmaxf(mx0, __shfl_xor_sync(0xffffffffu, mx0, 2, 4));
                mx1 = fmaxf(mx1, __shfl_xor_sync(0xffffffffu, mx1, 1, 4));
                mx1 = fmaxf(mx1, __shfl_xor_sync(0xffffffffu, mx1, 2, 4));

                if (q4 == 0) { red[redi] = mx0; red[128 + redi] = mx1; }
                barsync(1 + qw);
                float gm0 = mx0, gm1 = mx1;
#pragma unroll
                for (int d2 = 0; d2 < 4; d2++) {
                    gm0 = fmaxf(gm0, red[redbase + d2 * 8]);
                    gm1 = fmaxf(gm1, red[128 + redbase + d2 * 8]);
                }

                float mn0 = fmaxf(m0, gm0), mn1 = fmaxf(m1, gm1);
                float cr0 = __expf(m0 - mn0), cr1 = __expf(m1 - mn1);
                m0 = mn0; m1 = mn1;

                float sum0 = 0.f, sum1 = 0.f;
#pragma unroll
                for (int jl = 0; jl < 2; jl++) {
                    float p00 = __expf(cs[jl][0] - mn0), p01 = __expf(cs[jl][1] - mn0);
                    float p10 = __expf(cs[jl][2] - mn1), p11 = __expf(cs[jl][3] - mn1);
                    sum0 += p00 + p01; sum1 += p10 + p11;
                    *(__half2*)&Ps[g * PST + dw * 16 + 8 * jl + 2 * q4]       = __floats2half2_rn(p00, p01);
                    *(__half2*)&Ps[(g + 8) * PST + dw * 16 + 8 * jl + 2 * q4] = __floats2half2_rn(p10, p11);
                }
                sum0 += __shfl_xor_sync(0xffffffffu, sum0, 1, 4);
                sum0 += __shfl_xor_sync(0xffffffffu, sum0, 2, 4);
                sum1 += __shfl_xor_sync(0xffffffffu, sum1, 1, 4);
                sum1 += __shfl_xor_sync(0xffffffffu, sum1, 2, 4);
                l0 = l0 * cr0 + sum0;
                l1 = l1 * cr1 + sum1;

                if (!__all_sync(0xffffffffu, (cr0 == 1.f) & (cr1 == 1.f))) {
#pragma unroll
                    for (int j = 0; j < 12; j++) {
                        co[j][0] *= cr0; co[j][1] *= cr0;
                        co[j][2] *= cr1; co[j][3] *= cr1;
                    }
                }
                barsync(1 + qw);

#pragma unroll
                for (int kc = 0; kc < 4; kc++) {
                    uint32_t a[4];
                    ldsm4(a[0], a[1], a[2], a[3], psa + (uint32_t)(kc * 16) * 2);
#pragma unroll
                    for (int jp = 0; jp < 6; jp++) {
                        uint32_t b0, b1, b2, b3;
                        ldsm4t(b0, b1, b2, b3,
                               vtb + (uint32_t)(kc * 16 * VST + ((d0base + colT + jp * 16) ^ sw)) * 2);
                        mma16(co[2 * jp], a, b0, b1);
                        mma16(co[2 * jp + 1], a, b2, b3);
                    }
                }
            }
            __syncthreads();   // buffer ct-1 free for tile ct+1; protects red/P reuse
        }

        // pass epilogue: combine l partials across dw, write O
        if (q4 == 0) { red[redi] = l0; red[128 + redi] = l1; }
        __syncthreads();
        float L0 = 0.f, L1 = 0.f;
#pragma unroll
        for (int d2 = 0; d2 < 4; d2++) {
            L0 += red[redbase + d2 * 8];
            L1 += red[128 + redbase + d2 * 8];
        }

        const float i0 = 1.f / L0, i1 = 1.f / L1;
        float* O0 = O + ((size_t)b * TT + row0) * DD + d0base;
        float* O1 = O + ((size_t)b * TT + row1) * DD + d0base;
#pragma unroll
        for (int j = 0; j < 12; j++) {
            *(float2*)&O0[8 * j + 2 * q4] = make_float2(co[j][0] * i0, co[j][1] * i0);
            *(float2*)&O1[8 * j + 2 * q4] = make_float2(co[j][2] * i1, co[j][3] * i1);
        }
        __syncthreads();   // red safe for next pass
    }
}

extern "C" void kernel_launch(void* const* d_in, const int* in_sizes, int n_in,
                              void* d_out, int out_size)
{
    const float* x  = (const float*)d_in[0];
    const float* Wk = (const float*)d_in[1];
    const float* Wq = (const float*)d_in[2];
    const float* Wv = (const float*)d_in[3];
    float* out = (float*)d_out;

    to_half_all<<<XBLK + 2 * WBLK + VBLK, 256>>>(x, Wk, Wq, Wv);

    cudaFuncSetAttribute(proj_gemm, cudaFuncAttributeMaxDynamicSharedMemorySize, PROJ_SMEM_BYTES);
    proj_gemm<<<dim3(1, 128, 2), 256, PROJ_SMEM_BYTES>>>(0);
    proj_gemm<<<dim3(6, 128, 1), 256, PROJ_SMEM_BYTES>>>(2);

    cudaFuncSetAttribute(flash2, cudaFuncAttributeMaxDynamicSharedMemorySize, SMEM_BYTES);
    flash2<<<dim3(TT / BQ / 2, BB), 512, SMEM_BYTES>>>(out);
}

// round 16
// speedup vs baseline: 1.1769x; 1.0006x over previous
#include <cuda_runtime.h>
#include <cuda_fp16.h>
#include <math.h>
#include <stdint.h>

#define BB 4
#define TT 4096
#define DD 384
#define HD 64
#define BQ 64
#define BS 64

// Scratch (allocation-free). NEVER take these addresses in host code.
// g_k / g_v are stored XOR-swizzled: element (t,d) lives at column d ^ ((t&7)<<3).
__device__ __half g_xh[(size_t)BB * TT * DD];
__device__ __half g_wq[(size_t)HD * DD];
__device__ __half g_wk[(size_t)HD * DD];
__device__ __half g_wv[(size_t)DD * DD];
__device__ __half g_q[(size_t)BB * TT * HD];     // pre-scaled by 0.125 (via Wq), NOT swizzled
__device__ __half g_k[(size_t)BB * TT * HD];     // swizzled
__device__ __half g_v[(size_t)BB * TT * DD];     // swizzled, [b][t][d]

__device__ __forceinline__ void mma16(float* c, const uint32_t* a, uint32_t b0, uint32_t b1) {
    asm volatile(
        "mma.sync.aligned.m16n8k16.row.col.f32.f16.f16.f32 "
        "{%0,%1,%2,%3}, {%4,%5,%6,%7}, {%8,%9}, {%0,%1,%2,%3};\n"
        : "+f"(c[0]), "+f"(c[1]), "+f"(c[2]), "+f"(c[3])
        : "r"(a[0]), "r"(a[1]), "r"(a[2]), "r"(a[3]), "r"(b0), "r"(b1));
}

__device__ __forceinline__ void ldsm4(uint32_t& r0, uint32_t& r1, uint32_t& r2, uint32_t& r3,
                                      uint32_t addr) {
    asm volatile("ldmatrix.sync.aligned.m8n8.x4.shared.b16 {%0,%1,%2,%3}, [%4];"
                 : "=r"(r0), "=r"(r1), "=r"(r2), "=r"(r3) : "r"(addr) : "memory");
}

__device__ __forceinline__ void ldsm4t(uint32_t& r0, uint32_t& r1, uint32_t& r2, uint32_t& r3,
                                       uint32_t addr) {
    asm volatile("ldmatrix.sync.aligned.m8n8.x4.trans.shared.b16 {%0,%1,%2,%3}, [%4];"
                 : "=r"(r0), "=r"(r1), "=r"(r2), "=r"(r3) : "r"(addr) : "memory");
}

__device__ __forceinline__ void cp16(uint32_t dsh, const void* src) {
    asm volatile("cp.async.cg.shared.global [%0], [%1], 16;\n" :: "r"(dsh), "l"(src));
}

__device__ __forceinline__ void bulkcp(uint32_t dst, const void* src, uint32_t bytes, uint32_t mbar) {
    asm volatile("cp.async.bulk.shared::cta.global.mbarrier::complete_tx::bytes [%0], [%1], %2, [%3];"
                 :: "r"(dst), "l"(src), "r"(bytes), "r"(mbar) : "memory");
}

__device__ __forceinline__ void mbar_init(uint32_t mbar, uint32_t count) {
    asm volatile("mbarrier.init.shared.b64 [%0], %1;" :: "r"(mbar), "r"(count) : "memory");
}

__device__ __forceinline__ void mbar_expect_tx(uint32_t mbar, uint32_t bytes) {
    asm volatile("mbarrier.arrive.expect_tx.shared.b64 _, [%0], %1;" :: "r"(mbar), "r"(bytes) : "memory");
}

__device__ __forceinline__ void mbar_wait(uint32_t mbar, uint32_t parity) {
    asm volatile(
        "{\n\t.reg .pred P;\n\t"
        "WAIT_%=:\n\t"
        "mbarrier.try_wait.parity.acquire.cta.shared::cta.b64 P, [%0], %1, 0x989680;\n\t"
        "@!P bra WAIT_%=;\n\t"
        "}" :: "r"(mbar), "r"(parity) : "memory");
}

__device__ __forceinline__ void barsync(int id, int cnt) {
    asm volatile("bar.sync %0, %1;" :: "r"(id), "r"(cnt) : "memory");
}

// ---------------- fused fp32 -> fp16 conversion (one launch) ----------------
#define NX4 (BB * TT * DD / 4)
#define NW4 (HD * DD / 4)
#define NV4 (DD * DD / 4)
#define XBLK (NX4 / 256)
#define WBLK (NW4 / 256)
#define VBLK (NV4 / 256)

__global__ void __launch_bounds__(256) to_half_all(
    const float* __restrict__ x, const float* __restrict__ Wk,
    const float* __restrict__ Wq, const float* __restrict__ Wv)
{
    int bid = blockIdx.x;
    const float* s; __half* d; int base; float sc = 1.f;
    if (bid < XBLK)                  { s = x;  d = g_xh; base = 0; }
    else if (bid < XBLK + WBLK)      { s = Wq; d = g_wq; base = XBLK; sc = 0.125f; }
    else if (bid < XBLK + 2 * WBLK)  { s = Wk; d = g_wk; base = XBLK + WBLK; }
    else                             { s = Wv; d = g_wv; base = XBLK + 2 * WBLK; }
    int i = (bid - base) * 256 + threadIdx.x;
    float4 v = ((const float4*)s)[i];
    __half2 h0 = __floats2half2_rn(v.x * sc, v.y * sc);
    __half2 h1 = __floats2half2_rn(v.z * sc, v.w * sc);
    uint2 o;
    o.x = *(uint32_t*)&h0;
    o.y = *(uint32_t*)&h1;
    ((uint2*)d)[i] = o;
}

// ---------------- fp16 mma projection GEMM (k/v written swizzled) ----------------
#define XS 72
#define WS 72
#define X_TILE (128 * XS)
#define W_TILE (64 * WS)
#define PROJ_SMEM_HALFS (2 * (X_TILE + W_TILE))
#define PROJ_SMEM_BYTES (PROJ_SMEM_HALFS * 2)

__device__ __forceinline__ void proj_stage(__half* smp, const __half* X, const __half* W,
                                           int bm, int bn, int k0, int buf, int tid)
{
    __half* xb = smp + buf * (X_TILE + W_TILE);
    __half* wb = xb + X_TILE;
    uint32_t xbase = (uint32_t)__cvta_generic_to_shared(xb);
    uint32_t wbase = (uint32_t)__cvta_generic_to_shared(wb);
#pragma unroll
    for (int it = 0; it < 4; it++) {
        int i = tid + 256 * it;
        int r = i >> 3, c = i & 7;
        cp16(xbase + (uint32_t)(r * XS + c * 8) * 2,
             X + (size_t)(bm * 128 + r) * DD + k0 + c * 8);
    }
#pragma unroll
    for (int it = 0; it < 2; it++) {
        int i = tid + 256 * it;
        int r = i >> 3, c = i & 7;
        cp16(wbase + (uint32_t)(r * WS + c * 8) * 2,
             W + (size_t)(bn * 64 + r) * DD + k0 + c * 8);
    }
}

__global__ void __launch_bounds__(256) proj_gemm(int which_base)
{
    extern __shared__ __half smp[];
    const int z = blockIdx.z;
    const int which = which_base + z;
    const __half* X = g_xh;
    const __half* W = (which == 0) ? g_wq : (which == 1) ? g_wk : g_wv;
    __half* Y = (which == 0) ? g_q : (which == 1) ? g_k : g_v;
    const int N = (which < 2) ? HD : DD;

    const int bm = blockIdx.y;
    const int bn = blockIdx.x;
    const int tid = threadIdx.x;
    const int w = tid >> 5, l = tid & 31;
    const int wm = w >> 1, wn = w & 1;
    const int g = l >> 2, q4 = l & 3;

    float c[2][4][4];
#pragma unroll
    for (int mt = 0; mt < 2; mt++)
#pragma unroll
        for (int j = 0; j < 4; j++) { c[mt][j][0] = c[mt][j][1] = c[mt][j][2] = c[mt][j][3] = 0.f; }

    proj_stage(smp, X, W, bm, bn, 0, 0, tid);
    asm volatile("cp.async.commit_group;\n");

    const int nC = DD / 64;
    for (int cc = 0; cc < nC; cc++) {
        __syncthreads();
        if (cc + 1 < nC) {
            proj_stage(smp, X, W, bm, bn, (cc + 1) * 64, (cc + 1) & 1, tid);
            asm volatile("cp.async.commit_group;\n");
            asm volatile("cp.async.wait_group 1;\n");
        } else {
            asm volatile("cp.async.wait_group 0;\n");
        }
        __syncthreads();

        const __half* xb = smp + (cc & 1) * (X_TILE + W_TILE);
        const __half* wb = xb + X_TILE;
#pragma unroll
        for (int kk = 0; kk < 4; kk++) {
            const int k = kk * 16;
            uint32_t a[2][4];
#pragma unroll
            for (int mt = 0; mt < 2; mt++) {
                int r0 = wm * 32 + 16 * mt + g;
                a[mt][0] = *(const uint32_t*)&xb[r0 * XS + k + 2 * q4];
                a[mt][1] = *(const uint32_t*)&xb[(r0 + 8) * XS + k + 2 * q4];
                a[mt][2] = *(const uint32_t*)&xb[r0 * XS + k + 2 * q4 + 8];
                a[mt][3] = *(const uint32_t*)&xb[(r0 + 8) * XS + k + 2 * q4 + 8];
            }
#pragma unroll
            for (int j = 0; j < 4; j++) {
                int n = wn * 32 + 8 * j + g;
                uint32_t b0 = *(const uint32_t*)&wb[n * WS + k + 2 * q4];
                uint32_t b1 = *(const uint32_t*)&wb[n * WS + k + 2 * q4 + 8];
#pragma unroll
                for (int mt = 0; mt < 2; mt++) mma16(c[mt][j], a[mt], b0, b1);
            }
        }
    }

    const int swz = (which >= 1) ? (g << 3) : 0;
#pragma unroll
    for (int mt = 0; mt < 2; mt++) {
        int r0 = bm * 128 + wm * 32 + 16 * mt + g;
#pragma unroll
        for (int j = 0; j < 4; j++) {
            int col = (bn * 64 + wn * 32 + 8 * j + 2 * q4) ^ swz;
            *(__half2*)&Y[(size_t)r0 * N + col] = __floats2half2_rn(c[mt][j][0], c[mt][j][1]);
            *(__half2*)&Y[(size_t)(r0 + 8) * N + col] = __floats2half2_rn(c[mt][j][2], c[mt][j][3]);
        }
    }
}

// ---------------- flash attention: QK 4x4 mapping, PV 2x8 mapping (half V smem traffic) ----------------
#define VST 384
#define KST 64
#define PST 72
#define VT_TILE (64 * VST)
#define KS_TILE (64 * KST)
#define VT_OFF 0
#define KS_OFF (2 * VT_TILE)
#define PS_OFF (KS_OFF + 2 * KS_TILE)
#define SMEM_HALFS (PS_OFF + 4 * 16 * PST)
#define SMEM_BYTES (SMEM_HALFS * 2)
#define V_BYTES (64 * DD * 2)
#define K_BYTES (64 * HD * 2)
#define STAGE_BYTES (V_BYTES + K_BYTES)

__global__ void __launch_bounds__(512, 1) flash2(float* __restrict__ O)
{
    extern __shared__ __half smh[];
    __shared__ __align__(8) uint64_t fmbar[2];
    __shared__ float red[256];
    __shared__ float crbuf[64];

    const int b = blockIdx.y;
    const int bx = blockIdx.x;               // handles qb = 63-bx then qb = bx
    const int tid = threadIdx.x;
    const int w = tid >> 5, l = tid & 31;
    const int qw4 = w >> 2, dw4 = w & 3;     // QK mapping: 16-row group x 16-key split
    const int qw2 = w >> 3, dw8 = w & 7;     // PV mapping: 32-row group x 48-col split
    const int g = l >> 2, q4 = l & 3;

    const __half* Kb = g_k + (size_t)b * TT * HD;
    const __half* Vb = g_v + (size_t)b * TT * DD;

    __half* Ps = smh + PS_OFF + qw4 * (16 * PST);

    const uint32_t smb = (uint32_t)__cvta_generic_to_shared(smh);
    const uint32_t mb0 = (uint32_t)__cvta_generic_to_shared(&fmbar[0]);
    const uint32_t mb1 = (uint32_t)__cvta_generic_to_shared(&fmbar[1]);

    // ldmatrix lane geometry
    const int mm = l >> 3;
    const int rowB = (l & 7) + ((mm >> 1) << 3);   // K (non-trans B): t index
    const int colB = (mm & 1) << 3;
    const int rowA = (l & 7) + ((mm & 1) << 3);    // P (A)
    const int colA = (mm >> 1) << 3;
    const int rowT = (l & 7) + ((mm & 1) << 3);    // V (trans B): t index
    const int colT = (l >> 4) << 3;                // d index
    const int sw = (l & 7) << 3;                   // per-lane column swizzle (halfs)
    // PV A-fragment bases: P rows of QK groups 2*qw2 and 2*qw2+1
    const uint32_t psa0 = smb + (uint32_t)(PS_OFF + (2 * qw2) * 16 * PST + rowA * PST + colA) * 2;
    const uint32_t psa1 = psa0 + (uint32_t)(16 * PST) * 2;

    const int redi = (qw4 * 4 + dw4) * 8 + g;
    const int redbase = qw4 * 32 + g;
    const int d0base = dw8 * 48;

    if (tid == 0) {
        mbar_init(mb0, 1);
        mbar_init(mb1, 1);
        asm volatile("fence.proxy.async.shared::cta;" ::: "memory");
    }
    __syncthreads();

    // stage global tile 0 (pass 0, t = 0)
    if (tid == 0) {
        mbar_expect_tx(mb0, STAGE_BYTES);
        bulkcp(smb + (uint32_t)VT_OFF * 2, Vb, V_BYTES, mb0);
        bulkcp(smb + (uint32_t)KS_OFF * 2, Kb, K_BYTES, mb0);
    }
    int tc = 1;   // tiles staged
    int ct = 0;   // tiles consumed

#pragma unroll 1
    for (int pass = 0; pass < 2; pass++) {
        const int qb = pass ? bx : (63 - bx);
        const int q0 = qb * BQ;
        const int nT = qb + 1;
        const __half* Qb = g_q + ((size_t)b * TT + q0) * HD;

        uint32_t qa[4][4];
        const int qr0 = qw4 * 16 + g;
#pragma unroll
        for (int kk = 0; kk < 4; kk++) {
            qa[kk][0] = *(const uint32_t*)&Qb[(size_t)qr0 * HD + 16 * kk + 2 * q4];
            qa[kk][1] = *(const uint32_t*)&Qb[(size_t)(qr0 + 8) * HD + 16 * kk + 2 * q4];
            qa[kk][2] = *(const uint32_t*)&Qb[(size_t)qr0 * HD + 16 * kk + 2 * q4 + 8];
            qa[kk][3] = *(const uint32_t*)&Qb[(size_t)(qr0 + 8) * HD + 16 * kk + 2 * q4 + 8];
        }

        float co[12][4];   // [mt2*6 + jn]: rows qw2*32+mt2*16+{g,g+8}, cols d0base+8*jn
#pragma unroll
        for (int j = 0; j < 12; j++) { co[j][0] = co[j][1] = co[j][2] = co[j][3] = 0.f; }
        float m0 = -1e30f, m1 = -1e30f, l0 = 0.f, l1 = 0.f;

        const int row0 = q0 + qw4 * 16 + g;
        const int row1 = row0 + 8;

#pragma unroll 1
        for (int t = 0; t < nT; t++) {
            const bool have_next = (t + 1 < nT) || (pass == 0);
            if (have_next) {
                if (tid == 0) {
                    const int buf = tc & 1;
                    const uint32_t mb = buf ? mb1 : mb0;
                    const int s1 = (t + 1 < nT) ? (t + 1) * BS : 0;   // pass-1 tile 0
                    mbar_expect_tx(mb, STAGE_BYTES);
                    bulkcp(smb + (uint32_t)(VT_OFF + buf * VT_TILE) * 2,
                           Vb + (size_t)s1 * DD, V_BYTES, mb);
                    bulkcp(smb + (uint32_t)(KS_OFF + buf * KS_TILE) * 2,
                           Kb + (size_t)s1 * HD, K_BYTES, mb);
                }
                tc++;
            }

            const int cbuf = ct & 1;
            mbar_wait(cbuf ? mb1 : mb0, (ct >> 1) & 1);
            ct++;

            const int s0 = t * BS;
            const uint32_t ksb = smb + (uint32_t)(KS_OFF + cbuf * KS_TILE + rowB * KST) * 2;
            const uint32_t vtb = smb + (uint32_t)(VT_OFF + cbuf * VT_TILE + rowT * VST) * 2;

            // ---- S = Q K^T for this warp's 16 keys (QK mapping) ----
            float cs[2][4];
            cs[0][0] = cs[0][1] = cs[0][2] = cs[0][3] = 0.f;
            cs[1][0] = cs[1][1] = cs[1][2] = cs[1][3] = 0.f;
#pragma unroll
            for (int kk = 0; kk < 4; kk++) {
                uint32_t b0, b1, b2, b3;
                ldsm4(b0, b1, b2, b3,
                      ksb + (uint32_t)(dw4 * 16 * KST + ((colB + kk * 16) ^ sw)) * 2);
                mma16(cs[0], qa[kk], b0, b1);
                mma16(cs[1], qa[kk], b2, b3);
            }

            const bool needmask = (s0 + dw4 * 16 + 15) > (q0 + qw4 * 16);
            float mx0 = -1e30f, mx1 = -1e30f;
#pragma unroll
            for (int jl = 0; jl < 2; jl++) {
                int c0 = s0 + dw4 * 16 + 8 * jl + 2 * q4;
                float s00 = cs[jl][0], s01 = cs[jl][1];
                float s10 = cs[jl][2], s11 = cs[jl][3];
                if (needmask) {
                    if (c0 > row0)     s00 = -1e30f;
                    if (c0 + 1 > row0) s01 = -1e30f;
                    if (c0 > row1)     s10 = -1e30f;
                    if (c0 + 1 > row1) s11 = -1e30f;
                }
                cs[jl][0] = s00; cs[jl][1] = s01; cs[jl][2] = s10; cs[jl][3] = s11;
                mx0 = fmaxf(mx0, fmaxf(s00, s01));
                mx1 = fmaxf(mx1, fmaxf(s10, s11));
            }
            mx0 = fmaxf(mx0, __shfl_xor_sync(0xffffffffu, mx0, 1, 4));
            mx0 = fmaxf(mx0, __shfl_xor_sync(0xffffffffu, mx0, 2, 4));
            mx1 = fmaxf(mx1, __shfl_xor_sync(0xffffffffu, mx1, 1, 4));
            mx1 = fmaxf(mx1, __shfl_xor_sync(0xffffffffu, mx1, 2, 4));

            if (q4 == 0) { red[redi] = mx0; red[128 + redi] = mx1; }
            barsync(3 + qw4, 128);
            float gm0 = mx0, gm1 = mx1;
#pragma unroll
            for (int d2 = 0; d2 < 4; d2++) {
                gm0 = fmaxf(gm0, red[redbase + d2 * 8]);
                gm1 = fmaxf(gm1, red[128 + redbase + d2 * 8]);
            }

            float mn0 = fmaxf(m0, gm0), mn1 = fmaxf(m1, gm1);
            float cr0 = __expf(m0 - mn0), cr1 = __expf(m1 - mn1);
            m0 = mn0; m1 = mn1;

            // publish per-row rescale (identical across dw4 warps of a group)
            if (dw4 == 0 && q4 == 0) {
                crbuf[qw4 * 8 + g] = cr0;
                crbuf[32 + qw4 * 8 + g] = cr1;
            }

            float sum0 = 0.f, sum1 = 0.f;
#pragma unroll
            for (int jl = 0; jl < 2; jl++) {
                float p00 = __expf(cs[jl][0] - mn0), p01 = __expf(cs[jl][1] - mn0);
                float p10 = __expf(cs[jl][2] - mn1), p11 = __expf(cs[jl][3] - mn1);
                sum0 += p00 + p01; sum1 += p10 + p11;
                *(__half2*)&Ps[g * PST + dw4 * 16 + 8 * jl + 2 * q4]       = __floats2half2_rn(p00, p01);
                *(__half2*)&Ps[(g + 8) * PST + dw4 * 16 + 8 * jl + 2 * q4] = __floats2half2_rn(p10, p11);
            }
            sum0 += __shfl_xor_sync(0xffffffffu, sum0, 1, 4);
            sum0 += __shfl_xor_sync(0xffffffffu, sum0, 2, 4);
            sum1 += __shfl_xor_sync(0xffffffffu, sum1, 1, 4);
            sum1 += __shfl_xor_sync(0xffffffffu, sum1, 2, 4);
            l0 = l0 * cr0 + sum0;
            l1 = l1 * cr1 + sum1;

            // P + crbuf of both 16-row subgroups visible to the 256-thread qw2 pair
            barsync(1 + qw2, 256);

            // ---- PV (2x8 mapping): rescale then accumulate ----
            float crv0 = crbuf[(2 * qw2) * 8 + g];
            float crv1 = crbuf[32 + (2 * qw2) * 8 + g];
            float crv2 = crbuf[(2 * qw2 + 1) * 8 + g];
            float crv3 = crbuf[32 + (2 * qw2 + 1) * 8 + g];
            if (!__all_sync(0xffffffffu,
                            (crv0 == 1.f) & (crv1 == 1.f) & (crv2 == 1.f) & (crv3 == 1.f))) {
#pragma unroll
                for (int jn = 0; jn < 6; jn++) {
                    co[jn][0] *= crv0; co[jn][1] *= crv0;
                    co[jn][2] *= crv1; co[jn][3] *= crv1;
                    co[6 + jn][0] *= crv2; co[6 + jn][1] *= crv2;
                    co[6 + jn][2] *= crv3; co[6 + jn][3] *= crv3;
                }
            }

#pragma unroll
            for (int kc = 0; kc < 4; kc++) {
                uint32_t a0[4], a1[4];
                ldsm4(a0[0], a0[1], a0[2], a0[3], psa0 + (uint32_t)(kc * 16) * 2);
                ldsm4(a1[0], a1[1], a1[2], a1[3], psa1 + (uint32_t)(kc * 16) * 2);
#pragma unroll
                for (int jp = 0; jp < 3; jp++) {
                    uint32_t b0, b1, b2, b3;
                    ldsm4t(b0, b1, b2, b3,
                           vtb + (uint32_t)(kc * 16 * VST + ((d0base + colT + jp * 16) ^ sw)) * 2);
                    mma16(co[jp * 2],     a0, b0, b1);
                    mma16(co[jp * 2 + 1], a0, b2, b3);
                    mma16(co[6 + jp * 2],     a1, b0, b1);
                    mma16(co[6 + jp * 2 + 1], a1, b2, b3);
                }
            }
            __syncthreads();   // buffer recycle + red/P/crbuf reuse
        }

        // pass epilogue: combine l partials across dw4, write O with PV mapping
        if (q4 == 0) { red[redi] = l0; red[128 + redi] = l1; }
        __syncthreads();

#pragma unroll
        for (int mt2 = 0; mt2 < 2; mt2++) {
            const int gidx = 2 * qw2 + mt2;
            float L0 = 0.f, L1 = 0.f;
#pragma unroll
            for (int d2 = 0; d2 < 4; d2++) {
                L0 += red[gidx * 32 + d2 * 8 + g];
                L1 += red[128 + gidx * 32 + d2 * 8 + g];
            }
            const float i0 = 1.f / L0, i1 = 1.f / L1;
            const int rg = q0 + qw2 * 32 + mt2 * 16 + g;
            float* O0 = O + ((size_t)b * TT + rg) * DD + d0base;
            float* O1 = O + ((size_t)b * TT + rg + 8) * DD + d0base;
#pragma unroll
            for (int jn = 0; jn < 6; jn++) {
                *(float2*)&O0[8 * jn + 2 * q4] =
                    make_float2(co[mt2 * 6 + jn][0] * i0, co[mt2 * 6 + jn][1] * i0);
                *(float2*)&O1[8 * jn + 2 * q4] =
                    make_float2(co[mt2 * 6 + jn][2] * i1, co[mt2 * 6 + jn][3] * i1);
            }
        }
        __syncthreads();   // red safe for next pass
    }
}

extern "C" void kernel_launch(void* const* d_in, const int* in_sizes, int n_in,
                              void* d_out, int out_size)
{
    const float* x  = (const float*)d_in[0];
    const float* Wk = (const float*)d_in[1];
    const float* Wq = (const float*)d_in[2];
    const float* Wv = (const float*)d_in[3];
    float* out = (float*)d_out;

    to_half_all<<<XBLK + 2 * WBLK + VBLK, 256>>>(x, Wk, Wq, Wv);

    cudaFuncSetAttribute(proj_gemm, cudaFuncAttributeMaxDynamicSharedMemorySize, PROJ_SMEM_BYTES);
    proj_gemm<<<dim3(1, 128, 2), 256, PROJ_SMEM_BYTES>>>(0);
    proj_gemm<<<dim3(6, 128, 1), 256, PROJ_SMEM_BYTES>>>(2);

    cudaFuncSetAttribute(flash2, cudaFuncAttributeMaxDynamicSharedMemorySize, SMEM_BYTES);
    flash2<<<dim3(TT / BQ / 2, BB), 512, SMEM_BYTES>>>(out);
}

// round 17
// speedup vs baseline: 1.3123x; 1.1151x over previous
#include <cuda_runtime.h>
#include <cuda_fp16.h>
#include <math.h>
#include <stdint.h>

#define BB 4
#define TT 4096
#define DD 384
#define HD 64
#define BQ 64
#define BS 64

// Scratch (allocation-free). NEVER take these addresses in host code.
// g_k / g_v are stored XOR-swizzled: element (t,d) lives at column d ^ ((t&7)<<3).
__device__ __half g_xh[(size_t)BB * TT * DD];
__device__ __half g_wq[(size_t)HD * DD];
__device__ __half g_wk[(size_t)HD * DD];
__device__ __half g_wv[(size_t)DD * DD];
__device__ __half g_q[(size_t)BB * TT * HD];     // pre-scaled by 0.125 (via Wq), NOT swizzled
__device__ __half g_k[(size_t)BB * TT * HD];     // swizzled
__device__ __half g_v[(size_t)BB * TT * DD];     // swizzled, [b][t][d]

__device__ __forceinline__ void mma16(float* c, const uint32_t* a, uint32_t b0, uint32_t b1) {
    asm volatile(
        "mma.sync.aligned.m16n8k16.row.col.f32.f16.f16.f32 "
        "{%0,%1,%2,%3}, {%4,%5,%6,%7}, {%8,%9}, {%0,%1,%2,%3};\n"
        : "+f"(c[0]), "+f"(c[1]), "+f"(c[2]), "+f"(c[3])
        : "r"(a[0]), "r"(a[1]), "r"(a[2]), "r"(a[3]), "r"(b0), "r"(b1));
}

__device__ __forceinline__ void ldsm4(uint32_t& r0, uint32_t& r1, uint32_t& r2, uint32_t& r3,
                                      uint32_t addr) {
    asm volatile("ldmatrix.sync.aligned.m8n8.x4.shared.b16 {%0,%1,%2,%3}, [%4];"
                 : "=r"(r0), "=r"(r1), "=r"(r2), "=r"(r3) : "r"(addr) : "memory");
}

__device__ __forceinline__ void ldsm4t(uint32_t& r0, uint32_t& r1, uint32_t& r2, uint32_t& r3,
                                       uint32_t addr) {
    asm volatile("ldmatrix.sync.aligned.m8n8.x4.trans.shared.b16 {%0,%1,%2,%3}, [%4];"
                 : "=r"(r0), "=r"(r1), "=r"(r2), "=r"(r3) : "r"(addr) : "memory");
}

__device__ __forceinline__ void cp16(uint32_t dsh, const void* src) {
    asm volatile("cp.async.cg.shared.global [%0], [%1], 16;\n" :: "r"(dsh), "l"(src));
}

__device__ __forceinline__ void bulkcp(uint32_t dst, const void* src, uint32_t bytes, uint32_t mbar) {
    asm volatile("cp.async.bulk.shared::cta.global.mbarrier::complete_tx::bytes [%0], [%1], %2, [%3];"
                 :: "r"(dst), "l"(src), "r"(bytes), "r"(mbar) : "memory");
}

__device__ __forceinline__ void mbar_init(uint32_t mbar, uint32_t count) {
    asm volatile("mbarrier.init.shared.b64 [%0], %1;" :: "r"(mbar), "r"(count) : "memory");
}

__device__ __forceinline__ void mbar_expect_tx(uint32_t mbar, uint32_t bytes) {
    asm volatile("mbarrier.arrive.expect_tx.shared.b64 _, [%0], %1;" :: "r"(mbar), "r"(bytes) : "memory");
}

__device__ __forceinline__ void mbar_arrive(uint32_t mbar) {
    asm volatile("mbarrier.arrive.shared.b64 _, [%0];" :: "r"(mbar) : "memory");
}

__device__ __forceinline__ void mbar_wait(uint32_t mbar, uint32_t parity) {
    asm volatile(
        "{\n\t.reg .pred P;\n\t"
        "WAIT_%=:\n\t"
        "mbarrier.try_wait.parity.acquire.cta.shared::cta.b64 P, [%0], %1, 0x989680;\n\t"
        "@!P bra WAIT_%=;\n\t"
        "}" :: "r"(mbar), "r"(parity) : "memory");
}

__device__ __forceinline__ void barsync(int id, int cnt) {
    asm volatile("bar.sync %0, %1;" :: "r"(id), "r"(cnt) : "memory");
}

// ---------------- fused fp32 -> fp16 conversion (one launch) ----------------
#define NX4 (BB * TT * DD / 4)
#define NW4 (HD * DD / 4)
#define NV4 (DD * DD / 4)
#define XBLK (NX4 / 256)
#define WBLK (NW4 / 256)
#define VBLK (NV4 / 256)

__global__ void __launch_bounds__(256) to_half_all(
    const float* __restrict__ x, const float* __restrict__ Wk,
    const float* __restrict__ Wq, const float* __restrict__ Wv)
{
    int bid = blockIdx.x;
    const float* s; __half* d; int base; float sc = 1.f;
    if (bid < XBLK)                  { s = x;  d = g_xh; base = 0; }
    else if (bid < XBLK + WBLK)      { s = Wq; d = g_wq; base = XBLK; sc = 0.125f; }
    else if (bid < XBLK + 2 * WBLK)  { s = Wk; d = g_wk; base = XBLK + WBLK; }
    else                             { s = Wv; d = g_wv; base = XBLK + 2 * WBLK; }
    int i = (bid - base) * 256 + threadIdx.x;
    float4 v = ((const float4*)s)[i];
    __half2 h0 = __floats2half2_rn(v.x * sc, v.y * sc);
    __half2 h1 = __floats2half2_rn(v.z * sc, v.w * sc);
    uint2 o;
    o.x = *(uint32_t*)&h0;
    o.y = *(uint32_t*)&h1;
    ((uint2*)d)[i] = o;
}

// ---------------- fp16 mma projection GEMM, ONE launch (bn 0-5: v, 6: q, 7: k) ----------------
#define XS 72
#define WS 72
#define X_TILE (128 * XS)
#define W_TILE (64 * WS)
#define PROJ_SMEM_HALFS (2 * (X_TILE + W_TILE))
#define PROJ_SMEM_BYTES (PROJ_SMEM_HALFS * 2)

__device__ __forceinline__ void proj_stage(__half* smp, const __half* X, const __half* W,
                                           int bm, int bn, int k0, int buf, int tid)
{
    __half* xb = smp + buf * (X_TILE + W_TILE);
    __half* wb = xb + X_TILE;
    uint32_t xbase = (uint32_t)__cvta_generic_to_shared(xb);
    uint32_t wbase = (uint32_t)__cvta_generic_to_shared(wb);
#pragma unroll
    for (int it = 0; it < 4; it++) {
        int i = tid + 256 * it;
        int r = i >> 3, c = i & 7;
        cp16(xbase + (uint32_t)(r * XS + c * 8) * 2,
             X + (size_t)(bm * 128 + r) * DD + k0 + c * 8);
    }
#pragma unroll
    for (int it = 0; it < 2; it++) {
        int i = tid + 256 * it;
        int r = i >> 3, c = i & 7;
        cp16(wbase + (uint32_t)(r * WS + c * 8) * 2,
             W + (size_t)(bn * 64 + r) * DD + k0 + c * 8);
    }
}

__global__ void __launch_bounds__(256) proj_gemm()
{
    extern __shared__ __half smp[];
    const int bnr = blockIdx.x;                       // 0..7
    const int which = (bnr >= 6) ? (bnr - 6) : 2;     // 0=q,1=k,2=v
    const int bn = (bnr >= 6) ? 0 : bnr;
    const __half* X = g_xh;
    const __half* W = (which == 0) ? g_wq : (which == 1) ? g_wk : g_wv;
    __half* Y = (which == 0) ? g_q : (which == 1) ? g_k : g_v;
    const int N = (which < 2) ? HD : DD;

    const int bm = blockIdx.y;
    const int tid = threadIdx.x;
    const int w = tid >> 5, l = tid & 31;
    const int wm = w >> 1, wn = w & 1;
    const int g = l >> 2, q4 = l & 3;

    float c[2][4][4];
#pragma unroll
    for (int mt = 0; mt < 2; mt++)
#pragma unroll
        for (int j = 0; j < 4; j++) { c[mt][j][0] = c[mt][j][1] = c[mt][j][2] = c[mt][j][3] = 0.f; }

    proj_stage(smp, X, W, bm, bn, 0, 0, tid);
    asm volatile("cp.async.commit_group;\n");

    const int nC = DD / 64;
    for (int cc = 0; cc < nC; cc++) {
        __syncthreads();
        if (cc + 1 < nC) {
            proj_stage(smp, X, W, bm, bn, (cc + 1) * 64, (cc + 1) & 1, tid);
            asm volatile("cp.async.commit_group;\n");
            asm volatile("cp.async.wait_group 1;\n");
        } else {
            asm volatile("cp.async.wait_group 0;\n");
        }
        __syncthreads();

        const __half* xb = smp + (cc & 1) * (X_TILE + W_TILE);
        const __half* wb = xb + X_TILE;
#pragma unroll
        for (int kk = 0; kk < 4; kk++) {
            const int k = kk * 16;
            uint32_t a[2][4];
#pragma unroll
            for (int mt = 0; mt < 2; mt++) {
                int r0 = wm * 32 + 16 * mt + g;
                a[mt][0] = *(const uint32_t*)&xb[r0 * XS + k + 2 * q4];
                a[mt][1] = *(const uint32_t*)&xb[(r0 + 8) * XS + k + 2 * q4];
                a[mt][2] = *(const uint32_t*)&xb[r0 * XS + k + 2 * q4 + 8];
                a[mt][3] = *(const uint32_t*)&xb[(r0 + 8) * XS + k + 2 * q4 + 8];
            }
#pragma unroll
            for (int j = 0; j < 4; j++) {
                int n = wn * 32 + 8 * j + g;
                uint32_t b0 = *(const uint32_t*)&wb[n * WS + k + 2 * q4];
                uint32_t b1 = *(const uint32_t*)&wb[n * WS + k + 2 * q4 + 8];
#pragma unroll
                for (int mt = 0; mt < 2; mt++) mma16(c[mt][j], a[mt], b0, b1);
            }
        }
    }

    const int swz = (which >= 1) ? (g << 3) : 0;
#pragma unroll
    for (int mt = 0; mt < 2; mt++) {
        int r0 = bm * 128 + wm * 32 + 16 * mt + g;
#pragma unroll
        for (int j = 0; j < 4; j++) {
            int col = (bn * 64 + wn * 32 + 8 * j + 2 * q4) ^ swz;
            *(__half2*)&Y[(size_t)r0 * N + col] = __floats2half2_rn(c[mt][j][0], c[mt][j][1]);
            *(__half2*)&Y[(size_t)(r0 + 8) * N + col] = __floats2half2_rn(c[mt][j][2], c[mt][j][3]);
        }
    }
}

// ---------------- flash attention: async buffer recycle (no CTA-wide sync per tile) ----------------
#define VST 384
#define KST 64
#define PST 72
#define VT_TILE (64 * VST)
#define KS_TILE (64 * KST)
#define VT_OFF 0
#define KS_OFF (2 * VT_TILE)
#define PS_OFF (KS_OFF + 2 * KS_TILE)
#define SMEM_HALFS (PS_OFF + 4 * 16 * PST)
#define SMEM_BYTES (SMEM_HALFS * 2)
#define V_BYTES (64 * DD * 2)
#define K_BYTES (64 * HD * 2)
#define STAGE_BYTES (V_BYTES + K_BYTES)

__global__ void __launch_bounds__(512, 1) flash2(float* __restrict__ O)
{
    extern __shared__ __half smh[];
    __shared__ __align__(8) uint64_t fullb[2];
    __shared__ __align__(8) uint64_t emptyb[2];
    __shared__ float red[256];
    __shared__ float crbuf[64];

    const int b = blockIdx.y;
    const int bx = blockIdx.x;               // handles qb = 63-bx then qb = bx
    const int tid = threadIdx.x;
    const int w = tid >> 5, l = tid & 31;
    const int qw4 = w >> 2, dw4 = w & 3;     // QK mapping
    const int qw2 = w >> 3, dw8 = w & 7;     // PV mapping
    const int g = l >> 2, q4 = l & 3;

    const __half* Kb = g_k + (size_t)b * TT * HD;
    const __half* Vb = g_v + (size_t)b * TT * DD;

    __half* Ps = smh + PS_OFF + qw4 * (16 * PST);

    const uint32_t smb = (uint32_t)__cvta_generic_to_shared(smh);
    const uint32_t fb0 = (uint32_t)__cvta_generic_to_shared(&fullb[0]);
    const uint32_t fb1 = (uint32_t)__cvta_generic_to_shared(&fullb[1]);
    const uint32_t eb0 = (uint32_t)__cvta_generic_to_shared(&emptyb[0]);
    const uint32_t eb1 = (uint32_t)__cvta_generic_to_shared(&emptyb[1]);

    // ldmatrix lane geometry
    const int mm = l >> 3;
    const int rowB = (l & 7) + ((mm >> 1) << 3);
    const int colB = (mm & 1) << 3;
    const int rowA = (l & 7) + ((mm & 1) << 3);
    const int colA = (mm >> 1) << 3;
    const int rowT = (l & 7) + ((mm & 1) << 3);
    const int colT = (l >> 4) << 3;
    const int sw = (l & 7) << 3;
    const uint32_t psa0 = smb + (uint32_t)(PS_OFF + (2 * qw2) * 16 * PST + rowA * PST + colA) * 2;
    const uint32_t psa1 = psa0 + (uint32_t)(16 * PST) * 2;

    const int redi = (qw4 * 4 + dw4) * 8 + g;
    const int redbase = qw4 * 32 + g;
    const int d0base = dw8 * 48;

    if (tid == 0) {
        mbar_init(fb0, 1);
        mbar_init(fb1, 1);
        mbar_init(eb0, 16);          // one arrival per warp per consumption
        mbar_init(eb1, 16);
        asm volatile("fence.proxy.async.shared::cta;" ::: "memory");
    }
    __syncthreads();

    // stage global tile 0 into buffer 0
    if (tid == 0) {
        mbar_expect_tx(fb0, STAGE_BYTES);
        bulkcp(smb + (uint32_t)VT_OFF * 2, Vb, V_BYTES, fb0);
        bulkcp(smb + (uint32_t)KS_OFF * 2, Kb, K_BYTES, fb0);
    }
    int tc = 1;   // tiles staged
    int ct = 0;   // tiles consumed

#pragma unroll 1
    for (int pass = 0; pass < 2; pass++) {
        const int qb = pass ? bx : (63 - bx);
        const int q0 = qb * BQ;
        const int nT = qb + 1;
        const __half* Qb = g_q + ((size_t)b * TT + q0) * HD;

        uint32_t qa[4][4];
        const int qr0 = qw4 * 16 + g;
#pragma unroll
        for (int kk = 0; kk < 4; kk++) {
            qa[kk][0] = *(const uint32_t*)&Qb[(size_t)qr0 * HD + 16 * kk + 2 * q4];
            qa[kk][1] = *(const uint32_t*)&Qb[(size_t)(qr0 + 8) * HD + 16 * kk + 2 * q4];
            qa[kk][2] = *(const uint32_t*)&Qb[(size_t)qr0 * HD + 16 * kk + 2 * q4 + 8];
            qa[kk][3] = *(const uint32_t*)&Qb[(size_t)(qr0 + 8) * HD + 16 * kk + 2 * q4 + 8];
        }

        float co[12][4];
#pragma unroll
        for (int j = 0; j < 12; j++) { co[j][0] = co[j][1] = co[j][2] = co[j][3] = 0.f; }
        float m0 = -1e30f, m1 = -1e30f, l0 = 0.f, l1 = 0.f;

        const int row0 = q0 + qw4 * 16 + g;
        const int row1 = row0 + 8;

#pragma unroll 1
        for (int t = 0; t < nT; t++) {
            const bool have_next = (t + 1 < nT) || (pass == 0);
            if (have_next) {
                if (tid == 0) {
                    const int buf = tc & 1;
                    // wait until buffer free (tile tc-2 fully consumed)
                    if (tc >= 2) mbar_wait(buf ? eb1 : eb0, ((tc >> 1) - 1) & 1);
                    const uint32_t mb = buf ? fb1 : fb0;
                    const int s1 = (t + 1 < nT) ? (t + 1) * BS : 0;
                    mbar_expect_tx(mb, STAGE_BYTES);
                    bulkcp(smb + (uint32_t)(VT_OFF + buf * VT_TILE) * 2,
                           Vb + (size_t)s1 * DD, V_BYTES, mb);
                    bulkcp(smb + (uint32_t)(KS_OFF + buf * KS_TILE) * 2,
                           Kb + (size_t)s1 * HD, K_BYTES, mb);
                }
                tc++;
            }

            const int cbuf = ct & 1;
            mbar_wait(cbuf ? fb1 : fb0, (ct >> 1) & 1);

            const int s0 = t * BS;
            const uint32_t ksb = smb + (uint32_t)(KS_OFF + cbuf * KS_TILE + rowB * KST) * 2;
            const uint32_t vtb = smb + (uint32_t)(VT_OFF + cbuf * VT_TILE + rowT * VST) * 2;

            // ---- S = Q K^T for this warp's 16 keys ----
            float cs[2][4];
            cs[0][0] = cs[0][1] = cs[0][2] = cs[0][3] = 0.f;
            cs[1][0] = cs[1][1] = cs[1][2] = cs[1][3] = 0.f;
#pragma unroll
            for (int kk = 0; kk < 4; kk++) {
                uint32_t b0, b1, b2, b3;
                ldsm4(b0, b1, b2, b3,
                      ksb + (uint32_t)(dw4 * 16 * KST + ((colB + kk * 16) ^ sw)) * 2);
                mma16(cs[0], qa[kk], b0, b1);
                mma16(cs[1], qa[kk], b2, b3);
            }

            const bool needmask = (s0 + dw4 * 16 + 15) > (q0 + qw4 * 16);
            float mx0 = -1e30f, mx1 = -1e30f;
#pragma unroll
            for (int jl = 0; jl < 2; jl++) {
                int c0 = s0 + dw4 * 16 + 8 * jl + 2 * q4;
                float s00 = cs[jl][0], s01 = cs[jl][1];
                float s10 = cs[jl][2], s11 = cs[jl][3];
                if (needmask) {
                    if (c0 > row0)     s00 = -1e30f;
                    if (c0 + 1 > row0) s01 = -1e30f;
                    if (c0 > row1)     s10 = -1e30f;
                    if (c0 + 1 > row1) s11 = -1e30f;
                }
                cs[jl][0] = s00; cs[jl][1] = s01; cs[jl][2] = s10; cs[jl][3] = s11;
                mx0 = fmaxf(mx0, fmaxf(s00, s01));
                mx1 = fmaxf(mx1, fmaxf(s10, s11));
            }
            mx0 = fmaxf(mx0, __shfl_xor_sync(0xffffffffu, mx0, 1, 4));
            mx0 = fmaxf(mx0, __shfl_xor_sync(0xffffffffu, mx0, 2, 4));
            mx1 = fmaxf(mx1, __shfl_xor_sync(0xffffffffu, mx1, 1, 4));
            mx1 = fmaxf(mx1, __shfl_xor_sync(0xffffffffu, mx1, 2, 4));

            if (q4 == 0) { red[redi] = mx0; red[128 + redi] = mx1; }
            barsync(5 + qw4, 128);
            float gm0 = mx0, gm1 = mx1;
#pragma unroll
            for (int d2 = 0; d2 < 4; d2++) {
                gm0 = fmaxf(gm0, red[redbase + d2 * 8]);
                gm1 = fmaxf(gm1, red[128 + redbase + d2 * 8]);
            }

            float mn0 = fmaxf(m0, gm0), mn1 = fmaxf(m1, gm1);
            float cr0 = __expf(m0 - mn0), cr1 = __expf(m1 - mn1);
            m0 = mn0; m1 = mn1;

            if (dw4 == 0 && q4 == 0) {
                crbuf[qw4 * 8 + g] = cr0;
                crbuf[32 + qw4 * 8 + g] = cr1;
            }

            float sum0 = 0.f, sum1 = 0.f;
#pragma unroll
            for (int jl = 0; jl < 2; jl++) {
                float p00 = __expf(cs[jl][0] - mn0), p01 = __expf(cs[jl][1] - mn0);
                float p10 = __expf(cs[jl][2] - mn1), p11 = __expf(cs[jl][3] - mn1);
                sum0 += p00 + p01; sum1 += p10 + p11;
                *(__half2*)&Ps[g * PST + dw4 * 16 + 8 * jl + 2 * q4]       = __floats2half2_rn(p00, p01);
                *(__half2*)&Ps[(g + 8) * PST + dw4 * 16 + 8 * jl + 2 * q4] = __floats2half2_rn(p10, p11);
            }
            sum0 += __shfl_xor_sync(0xffffffffu, sum0, 1, 4);
            sum0 += __shfl_xor_sync(0xffffffffu, sum0, 2, 4);
            sum1 += __shfl_xor_sync(0xffffffffu, sum1, 1, 4);
            sum1 += __shfl_xor_sync(0xffffffffu, sum1, 2, 4);
            l0 = l0 * cr0 + sum0;
            l1 = l1 * cr1 + sum1;

            // P + crbuf of both 16-row subgroups visible to the 256-thread qw2 pair
            barsync(1 + qw2, 256);

            // ---- PV (2x8 mapping): rescale then accumulate ----
            float crv0 = crbuf[(2 * qw2) * 8 + g];
            float crv1 = crbuf[32 + (2 * qw2) * 8 + g];
            float crv2 = crbuf[(2 * qw2 + 1) * 8 + g];
            float crv3 = crbuf[32 + (2 * qw2 + 1) * 8 + g];
            if (!__all_sync(0xffffffffu,
                            (crv0 == 1.f) & (crv1 == 1.f) & (crv2 == 1.f) & (crv3 == 1.f))) {
#pragma unroll
                for (int jn = 0; jn < 6; jn++) {
                    co[jn][0] *= crv0; co[jn][1] *= crv0;
                    co[jn][2] *= crv1; co[jn][3] *= crv1;
                    co[6 + jn][0] *= crv2; co[6 + jn][1] *= crv2;
                    co[6 + jn][2] *= crv3; co[6 + jn][3] *= crv3;
                }
            }

#pragma unroll
            for (int kc = 0; kc < 4; kc++) {
                uint32_t a0[4], a1[4];
                ldsm4(a0[0], a0[1], a0[2], a0[3], psa0 + (uint32_t)(kc * 16) * 2);
                ldsm4(a1[0], a1[1], a1[2], a1[3], psa1 + (uint32_t)(kc * 16) * 2);
#pragma unroll
                for (int jp = 0; jp < 3; jp++) {
                    uint32_t b0, b1, b2, b3;
                    ldsm4t(b0, b1, b2, b3,
                           vtb + (uint32_t)(kc * 16 * VST + ((d0base + colT + jp * 16) ^ sw)) * 2);
                    mma16(co[jp * 2],     a0, b0, b1);
                    mma16(co[jp * 2 + 1], a0, b2, b3);
                    mma16(co[6 + jp * 2],     a1, b0, b1);
                    mma16(co[6 + jp * 2 + 1], a1, b2, b3);
                }
            }

            // buffer consumed (all this warp's K/V reads retired by mma deps)
            __syncwarp();
            if (l == 0) mbar_arrive(cbuf ? eb1 : eb0);
            ct++;

            // P consumed: safe for next tile's P writes (pair-local)
            barsync(3 + qw2, 256);
        }

        // pass epilogue: combine l partials across dw4 (pair-local), write O with PV mapping
        if (q4 == 0) { red[redi] = l0; red[128 + redi] = l1; }
        barsync(1 + qw2, 256);

#pragma unroll
        for (int mt2 = 0; mt2 < 2; mt2++) {
            const int gidx = 2 * qw2 + mt2;
            float L0 = 0.f, L1 = 0.f;
#pragma unroll
            for (int d2 = 0; d2 < 4; d2++) {
                L0 += red[gidx * 32 + d2 * 8 + g];
                L1 += red[128 + gidx * 32 + d2 * 8 + g];
            }
            const float i0 = 1.f / L0, i1 = 1.f / L1;
            const int rg = q0 + qw2 * 32 + mt2 * 16 + g;
            float* O0 = O + ((size_t)b * TT + rg) * DD + d0base;
            float* O1 = O + ((size_t)b * TT + rg + 8) * DD + d0base;
#pragma unroll
            for (int jn = 0; jn < 6; jn++) {
                *(float2*)&O0[8 * jn + 2 * q4] =
                    make_float2(co[mt2 * 6 + jn][0] * i0, co[mt2 * 6 + jn][1] * i0);
                *(float2*)&O1[8 * jn + 2 * q4] =
                    make_float2(co[mt2 * 6 + jn][2] * i1, co[mt2 * 6 + jn][3] * i1);
            }
        }
        // red slots safe for next pass (pair-local reuse)
        barsync(3 + qw2, 256);
    }
}

extern "C" void kernel_launch(void* const* d_in, const int* in_sizes, int n_in,
                              void* d_out, int out_size)
{
    const float* x  = (const float*)d_in[0];
    const float* Wk = (const float*)d_in[1];
    const float* Wq = (const float*)d_in[2];
    const float* Wv = (const float*)d_in[3];
    float* out = (float*)d_out;

    to_half_all<<<XBLK + 2 * WBLK + VBLK, 256>>>(x, Wk, Wq, Wv);

    cudaFuncSetAttribute(proj_gemm, cudaFuncAttributeMaxDynamicSharedMemorySize, PROJ_SMEM_BYTES);
    proj_gemm<<<dim3(8, 128), 256, PROJ_SMEM_BYTES>>>();

    cudaFuncSetAttribute(flash2, cudaFuncAttributeMaxDynamicSharedMemorySize, SMEM_BYTES);
    flash2<<<dim3(TT / BQ / 2, BB), 512, SMEM_BYTES>>>(out);
}